// round 9
// baseline (speedup 1.0000x reference)
#include <cuda_runtime.h>
#include <math.h>
#include <stdint.h>

// Problem constants
#define TOK   8192
#define DDIM  1024
#define FDIM  2048
#define NEXP  8
#define TOPK  2

#define BK    16
#define PBS   68     // B pair-row stride (BN=64), mult of 4 => conflict-free reads

// ---------------------------------------------------------------------------
// Scratch
// ---------------------------------------------------------------------------
__device__ int   g_count[NEXP];
__device__ int   g_rows [NEXP * TOK];
__device__ int   g_slot [NEXP * TOK];
__device__ float g_gate [TOK * TOPK];
__device__ float g_H    [(size_t)NEXP * TOK * FDIM];
__device__ float g_Y    [(size_t)TOK * TOPK * DDIM];

// ---------------------------------------------------------------------------
// tf32 helpers
// ---------------------------------------------------------------------------
__device__ __forceinline__ uint32_t f2tf32(float f) {
    uint32_t u;
    asm("cvt.rna.tf32.f32 %0, %1;" : "=r"(u) : "f"(f));
    return u;
}

__device__ __forceinline__ void mma4(float c[4], const uint4& a,
                                     uint32_t b0, uint32_t b1) {
    asm volatile(
        "mma.sync.aligned.m16n8k8.row.col.f32.tf32.tf32.f32 "
        "{%0,%1,%2,%3}, {%4,%5,%6,%7}, {%8,%9}, {%0,%1,%2,%3};"
        : "+f"(c[0]), "+f"(c[1]), "+f"(c[2]), "+f"(c[3])
        : "r"(a.x), "r"(a.y), "r"(a.z), "r"(a.w), "r"(b0), "r"(b1));
}

// Permuted A layout: fragment-order storage, swizzled (one LDS.128 per fragment).
__device__ __forceinline__ int a_off(int tm, int tk, int L, int comp) {
    int slot = ((L & ~3) | ((L & 3) ^ ((L >> 2) & 3))) ^ ((tm & 1) << 2);
    return ((tm * 2 + tk) * 32 + slot) * 4 + comp;
}

__device__ __forceinline__ void a_store(uint32_t* As, int row, int k, float v) {
    const int tm = row >> 4, r16 = row & 15;
    const int L = (r16 & 7) * 4 + (k & 3);
    const int comp = (r16 >> 3) + (((k >> 2) & 1) << 1);
    As[a_off(tm, k >> 3, L, comp)] = f2tf32(v);
}

// ---------------------------------------------------------------------------
// 0) zero expert counters
// ---------------------------------------------------------------------------
__global__ void zero_counts_kernel() {
    if (threadIdx.x < NEXP) g_count[threadIdx.x] = 0;
}

// ---------------------------------------------------------------------------
// 1) Router (one warp per token)
// ---------------------------------------------------------------------------
__global__ __launch_bounds__(256) void router_kernel(const float* __restrict__ x,
                                                     const float* __restrict__ Wg) {
    const int warp = (blockIdx.x * blockDim.x + threadIdx.x) >> 5;
    const int lane = threadIdx.x & 31;
    if (warp >= TOK) return;

    const float* xr = x + (size_t)warp * DDIM;
    float acc[NEXP];
#pragma unroll
    for (int e = 0; e < NEXP; e++) acc[e] = 0.f;

    for (int d = lane; d < DDIM; d += 32) {
        const float xv = xr[d];
        const float4 w0 = *reinterpret_cast<const float4*>(Wg + (size_t)d * NEXP);
        const float4 w1 = *reinterpret_cast<const float4*>(Wg + (size_t)d * NEXP + 4);
        acc[0] += xv * w0.x; acc[1] += xv * w0.y; acc[2] += xv * w0.z; acc[3] += xv * w0.w;
        acc[4] += xv * w1.x; acc[5] += xv * w1.y; acc[6] += xv * w1.z; acc[7] += xv * w1.w;
    }
#pragma unroll
    for (int off = 16; off > 0; off >>= 1) {
#pragma unroll
        for (int e = 0; e < NEXP; e++)
            acc[e] += __shfl_xor_sync(0xFFFFFFFFu, acc[e], off);
    }

    if (lane == 0) {
        int i0 = 0; float v0 = acc[0];
#pragma unroll
        for (int e = 1; e < NEXP; e++) if (acc[e] > v0) { v0 = acc[e]; i0 = e; }
        int i1 = -1; float v1 = -INFINITY;
#pragma unroll
        for (int e = 0; e < NEXP; e++)
            if (e != i0 && acc[e] > v1) { v1 = acc[e]; i1 = e; }

        const float e1 = expf(v1 - v0);
        const float inv = 1.f / (1.f + e1);
        g_gate[warp * 2 + 0] = inv;
        g_gate[warp * 2 + 1] = e1 * inv;

        int p0 = atomicAdd(&g_count[i0], 1);
        g_rows[i0 * TOK + p0] = warp;
        g_slot[i0 * TOK + p0] = warp * 2;
        int p1 = atomicAdd(&g_count[i1], 1);
        g_rows[i1 * TOK + p1] = warp;
        g_slot[i1 * TOK + p1] = warp * 2 + 1;
    }
}

// ---------------------------------------------------------------------------
// 2) Grouped dual GEMM + SwiGLU. Block 128x64, 8 warps (4m x 2n),
//    warp tile 32x32 dual. 2 CTAs/SM target.
// ---------------------------------------------------------------------------
__global__ __launch_bounds__(256, 2) void gemm1_kernel(const float* __restrict__ x,
                                                       const float* __restrict__ W1,
                                                       const float* __restrict__ W3) {
    const int e   = blockIdx.y >> 6;
    const int mt  = blockIdx.y & 63;
    const int cnt = g_count[e];
    const int m0  = mt * 128;
    if (m0 >= cnt) return;
    const int n0 = blockIdx.x * 64;

    __shared__ uint32_t As [2][2048];          // 128x16 tf32, permuted
    __shared__ uint32_t B1s[2][8 * PBS * 2];   // k-paired
    __shared__ uint32_t B3s[2][8 * PBS * 2];

    const int tid  = threadIdx.x;
    const int warp = tid >> 5;
    const int lane = tid & 31;
    const int wm = warp >> 1;       // 0..3
    const int wn = warp & 1;        // 0..1
    const int g  = lane >> 2;
    const int t  = lane & 3;

    // A loader: rows 0..127, each thread loads 8 floats of one row
    const int rA = tid >> 1;              // 0..127
    const int kA = (tid & 1) * 8;         // 0 or 8
    const bool av  = (m0 + rA < cnt);
    const int  tok = av ? g_rows[e * TOK + m0 + rA] : 0;
    const float* pA = x + (size_t)tok * DDIM + kA;

    // B loader: warp kq handles pair rows (r0, r0+4); lane = col (+32)
    const int kq = warp;
    const int r0 = (kq >> 2) * 8 + (kq & 3);
    const int r1 = r0 + 4;
    const float* pB1 = W1 + (size_t)e * DDIM * FDIM + n0;
    const float* pB3 = W3 + (size_t)e * DDIM * FDIM + n0;

    float acc1[2][4][4], acc3[2][4][4];
#pragma unroll
    for (int i = 0; i < 2; i++)
#pragma unroll
        for (int j = 0; j < 4; j++)
#pragma unroll
            for (int r = 0; r < 4; r++) { acc1[i][j][r] = 0.f; acc3[i][j][r] = 0.f; }

    float4 aq[2];
    float b1v[4], b3v[4];

    // prefetch k0 = 0 and fill buffer 0
    {
        aq[0] = *reinterpret_cast<const float4*>(pA);
        aq[1] = *reinterpret_cast<const float4*>(pA + 4);
        const float* b1r0 = pB1 + (size_t)r0 * FDIM;
        const float* b1r1 = pB1 + (size_t)r1 * FDIM;
        const float* b3r0 = pB3 + (size_t)r0 * FDIM;
        const float* b3r1 = pB3 + (size_t)r1 * FDIM;
        b1v[0] = b1r0[lane]; b1v[1] = b1r0[lane + 32];
        b1v[2] = b1r1[lane]; b1v[3] = b1r1[lane + 32];
        b3v[0] = b3r0[lane]; b3v[1] = b3r0[lane + 32];
        b3v[2] = b3r1[lane]; b3v[3] = b3r1[lane + 32];

#pragma unroll
        for (int q = 0; q < 2; q++) {
            a_store(As[0], rA, kA + q * 4 + 0, aq[q].x);
            a_store(As[0], rA, kA + q * 4 + 1, aq[q].y);
            a_store(As[0], rA, kA + q * 4 + 2, aq[q].z);
            a_store(As[0], rA, kA + q * 4 + 3, aq[q].w);
        }
        *reinterpret_cast<uint2*>(&B1s[0][(kq * PBS + lane) * 2]) =
            make_uint2(f2tf32(b1v[0]), f2tf32(b1v[2]));
        *reinterpret_cast<uint2*>(&B1s[0][(kq * PBS + lane + 32) * 2]) =
            make_uint2(f2tf32(b1v[1]), f2tf32(b1v[3]));
        *reinterpret_cast<uint2*>(&B3s[0][(kq * PBS + lane) * 2]) =
            make_uint2(f2tf32(b3v[0]), f2tf32(b3v[2]));
        *reinterpret_cast<uint2*>(&B3s[0][(kq * PBS + lane + 32) * 2]) =
            make_uint2(f2tf32(b3v[1]), f2tf32(b3v[3]));
    }
    __syncthreads();

    int p = 0;
    for (int k0 = 0; k0 < DDIM; k0 += BK) {
        const bool has_next = (k0 + BK < DDIM);
        if (has_next) {
            const int kn = k0 + BK;
            aq[0] = *reinterpret_cast<const float4*>(pA + kn);
            aq[1] = *reinterpret_cast<const float4*>(pA + kn + 4);
            const float* b1r0 = pB1 + (size_t)(kn + r0) * FDIM;
            const float* b1r1 = pB1 + (size_t)(kn + r1) * FDIM;
            const float* b3r0 = pB3 + (size_t)(kn + r0) * FDIM;
            const float* b3r1 = pB3 + (size_t)(kn + r1) * FDIM;
            b1v[0] = b1r0[lane]; b1v[1] = b1r0[lane + 32];
            b1v[2] = b1r1[lane]; b1v[3] = b1r1[lane + 32];
            b3v[0] = b3r0[lane]; b3v[1] = b3r0[lane + 32];
            b3v[2] = b3r1[lane]; b3v[3] = b3r1[lane + 32];
        }

#pragma unroll
        for (int ks = 0; ks < 2; ks++) {
            uint4 af[2];
#pragma unroll
            for (int i = 0; i < 2; i++) {
                const int tm = wm * 2 + i;
                af[i] = *reinterpret_cast<const uint4*>(&As[p][a_off(tm, ks, lane, 0)]);
            }
#pragma unroll
            for (int j = 0; j < 4; j++) {
                const int col = wn * 32 + j * 8 + g;
                const uint2 p1 = *reinterpret_cast<const uint2*>(
                    &B1s[p][((ks * 4 + t) * PBS + col) * 2]);
                const uint2 p3 = *reinterpret_cast<const uint2*>(
                    &B3s[p][((ks * 4 + t) * PBS + col) * 2]);
#pragma unroll
                for (int i = 0; i < 2; i++) {
                    mma4(acc1[i][j], af[i], p1.x, p1.y);
                    mma4(acc3[i][j], af[i], p3.x, p3.y);
                }
            }
        }

        if (has_next) {
            const int q1 = p ^ 1;
#pragma unroll
            for (int q = 0; q < 2; q++) {
                a_store(As[q1], rA, kA + q * 4 + 0, aq[q].x);
                a_store(As[q1], rA, kA + q * 4 + 1, aq[q].y);
                a_store(As[q1], rA, kA + q * 4 + 2, aq[q].z);
                a_store(As[q1], rA, kA + q * 4 + 3, aq[q].w);
            }
            *reinterpret_cast<uint2*>(&B1s[q1][(kq * PBS + lane) * 2]) =
                make_uint2(f2tf32(b1v[0]), f2tf32(b1v[2]));
            *reinterpret_cast<uint2*>(&B1s[q1][(kq * PBS + lane + 32) * 2]) =
                make_uint2(f2tf32(b1v[1]), f2tf32(b1v[3]));
            *reinterpret_cast<uint2*>(&B3s[q1][(kq * PBS + lane) * 2]) =
                make_uint2(f2tf32(b3v[0]), f2tf32(b3v[2]));
            *reinterpret_cast<uint2*>(&B3s[q1][(kq * PBS + lane + 32) * 2]) =
                make_uint2(f2tf32(b3v[1]), f2tf32(b3v[3]));
            __syncthreads();
        }
        p ^= 1;
    }

    float* Hbase = g_H + (size_t)e * TOK * FDIM;
    const int lim = cnt - m0;
#pragma unroll
    for (int i = 0; i < 2; i++) {
        const int lrow0 = wm * 32 + i * 16 + g;
        const int lrow1 = lrow0 + 8;
#pragma unroll
        for (int j = 0; j < 4; j++) {
            const int col = n0 + wn * 32 + j * 8 + 2 * t;
            if (lrow0 < lim) {
                const float z0 = acc1[i][j][0], z1 = acc1[i][j][1];
                float2 hv;
                hv.x = (z0 / (1.f + expf(-z0))) * acc3[i][j][0];
                hv.y = (z1 / (1.f + expf(-z1))) * acc3[i][j][1];
                *reinterpret_cast<float2*>(Hbase + (size_t)(m0 + lrow0) * FDIM + col) = hv;
            }
            if (lrow1 < lim) {
                const float z2 = acc1[i][j][2], z3 = acc1[i][j][3];
                float2 hv;
                hv.x = (z2 / (1.f + expf(-z2))) * acc3[i][j][2];
                hv.y = (z3 / (1.f + expf(-z3))) * acc3[i][j][3];
                *reinterpret_cast<float2*>(Hbase + (size_t)(m0 + lrow1) * FDIM + col) = hv;
            }
        }
    }
}

// ---------------------------------------------------------------------------
// 3) Grouped GEMM2. Block 256x64, 8 warps (4m x 2n), warp tile 64x32.
//    2 CTAs/SM target.
// ---------------------------------------------------------------------------
__global__ __launch_bounds__(256, 2) void gemm2_kernel(const float* __restrict__ W2) {
    const int e   = blockIdx.y >> 5;
    const int mt  = blockIdx.y & 31;
    const int cnt = g_count[e];
    const int m0  = mt * 256;
    if (m0 >= cnt) return;
    const int n0 = blockIdx.x * 64;

    __shared__ uint32_t As[2][4096];
    __shared__ uint32_t Bs[2][8 * PBS * 2];

    const int tid  = threadIdx.x;
    const int warp = tid >> 5;
    const int lane = tid & 31;
    const int wm = warp >> 1;
    const int wn = warp & 1;
    const int g  = lane >> 2;
    const int t  = lane & 3;

    // A loader: one H row per thread (rows >= cnt produce discarded outputs)
    const float* pA = g_H + ((size_t)e * TOK + (m0 + tid)) * FDIM;

    const int kq = warp;
    const int r0 = (kq >> 2) * 8 + (kq & 3);
    const int r1 = r0 + 4;
    const float* pB = W2 + (size_t)e * FDIM * DDIM + n0;

    float acc[4][4][4];
#pragma unroll
    for (int i = 0; i < 4; i++)
#pragma unroll
        for (int j = 0; j < 4; j++)
#pragma unroll
            for (int r = 0; r < 4; r++) acc[i][j][r] = 0.f;

    float4 aq[4];
    float bv[4];

    {
#pragma unroll
        for (int q = 0; q < 4; q++)
            aq[q] = *reinterpret_cast<const float4*>(pA + q * 4);
        const float* br0 = pB + (size_t)r0 * DDIM;
        const float* br1 = pB + (size_t)r1 * DDIM;
        bv[0] = br0[lane]; bv[1] = br0[lane + 32];
        bv[2] = br1[lane]; bv[3] = br1[lane + 32];
#pragma unroll
        for (int q = 0; q < 4; q++) {
            a_store(As[0], tid, q * 4 + 0, aq[q].x);
            a_store(As[0], tid, q * 4 + 1, aq[q].y);
            a_store(As[0], tid, q * 4 + 2, aq[q].z);
            a_store(As[0], tid, q * 4 + 3, aq[q].w);
        }
        *reinterpret_cast<uint2*>(&Bs[0][(kq * PBS + lane) * 2]) =
            make_uint2(f2tf32(bv[0]), f2tf32(bv[2]));
        *reinterpret_cast<uint2*>(&Bs[0][(kq * PBS + lane + 32) * 2]) =
            make_uint2(f2tf32(bv[1]), f2tf32(bv[3]));
    }
    __syncthreads();

    int p = 0;
    for (int k0 = 0; k0 < FDIM; k0 += BK) {
        const bool has_next = (k0 + BK < FDIM);
        if (has_next) {
            const int kn = k0 + BK;
#pragma unroll
            for (int q = 0; q < 4; q++)
                aq[q] = *reinterpret_cast<const float4*>(pA + kn + q * 4);
            const float* br0 = pB + (size_t)(kn + r0) * DDIM;
            const float* br1 = pB + (size_t)(kn + r1) * DDIM;
            bv[0] = br0[lane]; bv[1] = br0[lane + 32];
            bv[2] = br1[lane]; bv[3] = br1[lane + 32];
        }

#pragma unroll
        for (int ks = 0; ks < 2; ks++) {
            uint4 af[4];
#pragma unroll
            for (int i = 0; i < 4; i++) {
                const int tm = wm * 4 + i;
                af[i] = *reinterpret_cast<const uint4*>(&As[p][a_off(tm, ks, lane, 0)]);
            }
#pragma unroll
            for (int j = 0; j < 4; j++) {
                const int col = wn * 32 + j * 8 + g;
                const uint2 pr = *reinterpret_cast<const uint2*>(
                    &Bs[p][((ks * 4 + t) * PBS + col) * 2]);
#pragma unroll
                for (int i = 0; i < 4; i++)
                    mma4(acc[i][j], af[i], pr.x, pr.y);
            }
        }

        if (has_next) {
            const int q1 = p ^ 1;
#pragma unroll
            for (int q = 0; q < 4; q++) {
                a_store(As[q1], tid, q * 4 + 0, aq[q].x);
                a_store(As[q1], tid, q * 4 + 1, aq[q].y);
                a_store(As[q1], tid, q * 4 + 2, aq[q].z);
                a_store(As[q1], tid, q * 4 + 3, aq[q].w);
            }
            *reinterpret_cast<uint2*>(&Bs[q1][(kq * PBS + lane) * 2]) =
                make_uint2(f2tf32(bv[0]), f2tf32(bv[2]));
            *reinterpret_cast<uint2*>(&Bs[q1][(kq * PBS + lane + 32) * 2]) =
                make_uint2(f2tf32(bv[1]), f2tf32(bv[3]));
            __syncthreads();
        }
        p ^= 1;
    }

    const int lim = cnt - m0;
#pragma unroll
    for (int i = 0; i < 4; i++) {
        const int lrow0 = wm * 64 + i * 16 + g;
        const int lrow1 = lrow0 + 8;
        const int slot0 = (lrow0 < lim) ? g_slot[e * TOK + m0 + lrow0] : -1;
        const int slot1 = (lrow1 < lim) ? g_slot[e * TOK + m0 + lrow1] : -1;
#pragma unroll
        for (int j = 0; j < 4; j++) {
            const int col = n0 + wn * 32 + j * 8 + 2 * t;
            if (slot0 >= 0)
                *reinterpret_cast<float2*>(g_Y + (size_t)slot0 * DDIM + col) =
                    make_float2(acc[i][j][0], acc[i][j][1]);
            if (slot1 >= 0)
                *reinterpret_cast<float2*>(g_Y + (size_t)slot1 * DDIM + col) =
                    make_float2(acc[i][j][2], acc[i][j][3]);
        }
    }
}

// ---------------------------------------------------------------------------
// 4) Combine
// ---------------------------------------------------------------------------
__global__ __launch_bounds__(256) void combine_kernel(float* __restrict__ out) {
    const int tk = blockIdx.x;
    const int d = threadIdx.x * 4;
    const float g0 = g_gate[tk * 2 + 0];
    const float g1 = g_gate[tk * 2 + 1];
    const float4 y0 = *reinterpret_cast<const float4*>(g_Y + ((size_t)tk * 2 + 0) * DDIM + d);
    const float4 y1 = *reinterpret_cast<const float4*>(g_Y + ((size_t)tk * 2 + 1) * DDIM + d);
    float4 o;
    o.x = g0 * y0.x + g1 * y1.x;
    o.y = g0 * y0.y + g1 * y1.y;
    o.z = g0 * y0.z + g1 * y1.z;
    o.w = g0 * y0.w + g1 * y1.w;
    *reinterpret_cast<float4*>(out + (size_t)tk * DDIM + d) = o;
}

// ---------------------------------------------------------------------------
// Entry
// ---------------------------------------------------------------------------
extern "C" void kernel_launch(void* const* d_in, const int* in_sizes, int n_in,
                              void* d_out, int out_size) {
    const float* x  = (const float*)d_in[0];
    const float* Wg = (const float*)d_in[1];
    const float* W1 = (const float*)d_in[2];
    const float* W3 = (const float*)d_in[3];
    const float* W2 = (const float*)d_in[4];
    float* out = (float*)d_out;

    zero_counts_kernel<<<1, 32>>>();
    router_kernel<<<TOK / 8, 256>>>(x, Wg);
    gemm1_kernel<<<dim3(FDIM / 64, NEXP * (TOK / 128)), 256>>>(x, W1, W3);
    gemm2_kernel<<<dim3(DDIM / 64, NEXP * (TOK / 256)), 256>>>(W2);
    combine_kernel<<<TOK, 256>>>(out);
}

// round 10
// speedup vs baseline: 2.0829x; 2.0829x over previous
#include <cuda_runtime.h>
#include <math.h>
#include <stdint.h>

// Problem constants
#define TOK   8192
#define DDIM  1024
#define FDIM  2048
#define NEXP  8
#define TOPK  2

#define BK    32
#define PBS1  68     // B pair-row stride (BN=64);  stride*2 mod 32 == 8 -> conflict-free reads
#define PBS2  132    // B pair-row stride (BN=128); same property

// ---------------------------------------------------------------------------
// Scratch
// ---------------------------------------------------------------------------
__device__ int   g_count[NEXP];
__device__ int   g_rows [NEXP * TOK];
__device__ int   g_slot [NEXP * TOK];
__device__ float g_gate [TOK * TOPK];
__device__ float g_H    [(size_t)NEXP * TOK * FDIM];
__device__ float g_Y    [(size_t)TOK * TOPK * DDIM];

// ---------------------------------------------------------------------------
// tf32 helpers
// ---------------------------------------------------------------------------
__device__ __forceinline__ uint32_t f2tf32(float f) {
    uint32_t u;
    asm("cvt.rna.tf32.f32 %0, %1;" : "=r"(u) : "f"(f));
    return u;
}

__device__ __forceinline__ void mma4(float c[4], const uint4& a,
                                     uint32_t b0, uint32_t b1) {
    asm volatile(
        "mma.sync.aligned.m16n8k8.row.col.f32.tf32.tf32.f32 "
        "{%0,%1,%2,%3}, {%4,%5,%6,%7}, {%8,%9}, {%0,%1,%2,%3};"
        : "+f"(c[0]), "+f"(c[1]), "+f"(c[2]), "+f"(c[3])
        : "r"(a.x), "r"(a.y), "r"(a.z), "r"(a.w), "r"(b0), "r"(b1));
}

// Permuted A layout (fragment-order, swizzled). Tile (tm: 16 rows, tk: 8 k).
// Lane L owns {A[16tm+g][8tk+t], A[16tm+g+8][..], A[..][t+4], A[..][t+4]} as uint4.
__device__ __forceinline__ int a_off(int tm, int tk, int L, int comp) {
    int slot = (((L & ~3) | ((L & 3) ^ ((L >> 2) & 3))) ^ ((tm & 1) << 2)) ^ tk;
    return ((tm * 4 + tk) * 32 + slot) * 4 + comp;
}

__device__ __forceinline__ void a_store(uint32_t* As, int row, int k, float v) {
    const int tm = row >> 4, r16 = row & 15;
    const int L = (r16 & 7) * 4 + (k & 3);
    const int comp = (r16 >> 3) + (((k >> 2) & 1) << 1);
    As[a_off(tm, (k >> 3) & 3, L, comp)] = f2tf32(v);
}

// ---------------------------------------------------------------------------
// 0) zero expert counters
// ---------------------------------------------------------------------------
__global__ void zero_counts_kernel() {
    if (threadIdx.x < NEXP) g_count[threadIdx.x] = 0;
}

// ---------------------------------------------------------------------------
// 1) Router (one warp per token)
// ---------------------------------------------------------------------------
__global__ __launch_bounds__(256) void router_kernel(const float* __restrict__ x,
                                                     const float* __restrict__ Wg) {
    const int warp = (blockIdx.x * blockDim.x + threadIdx.x) >> 5;
    const int lane = threadIdx.x & 31;
    if (warp >= TOK) return;

    const float* xr = x + (size_t)warp * DDIM;
    float acc[NEXP];
#pragma unroll
    for (int e = 0; e < NEXP; e++) acc[e] = 0.f;

    for (int d = lane; d < DDIM; d += 32) {
        const float xv = xr[d];
        const float4 w0 = *reinterpret_cast<const float4*>(Wg + (size_t)d * NEXP);
        const float4 w1 = *reinterpret_cast<const float4*>(Wg + (size_t)d * NEXP + 4);
        acc[0] += xv * w0.x; acc[1] += xv * w0.y; acc[2] += xv * w0.z; acc[3] += xv * w0.w;
        acc[4] += xv * w1.x; acc[5] += xv * w1.y; acc[6] += xv * w1.z; acc[7] += xv * w1.w;
    }
#pragma unroll
    for (int off = 16; off > 0; off >>= 1) {
#pragma unroll
        for (int e = 0; e < NEXP; e++)
            acc[e] += __shfl_xor_sync(0xFFFFFFFFu, acc[e], off);
    }

    if (lane == 0) {
        int i0 = 0; float v0 = acc[0];
#pragma unroll
        for (int e = 1; e < NEXP; e++) if (acc[e] > v0) { v0 = acc[e]; i0 = e; }
        int i1 = -1; float v1 = -INFINITY;
#pragma unroll
        for (int e = 0; e < NEXP; e++)
            if (e != i0 && acc[e] > v1) { v1 = acc[e]; i1 = e; }

        const float e1 = expf(v1 - v0);
        const float inv = 1.f / (1.f + e1);
        g_gate[warp * 2 + 0] = inv;
        g_gate[warp * 2 + 1] = e1 * inv;

        int p0 = atomicAdd(&g_count[i0], 1);
        g_rows[i0 * TOK + p0] = warp;
        g_slot[i0 * TOK + p0] = warp * 2;
        int p1 = atomicAdd(&g_count[i1], 1);
        g_rows[i1 * TOK + p1] = warp;
        g_slot[i1 * TOK + p1] = warp * 2 + 1;
    }
}

// ---------------------------------------------------------------------------
// 2) Grouped dual GEMM + SwiGLU. Block 256x64, 8 warps (4m x 2n), warp 64x32
//    dual. BK=32 chunks, coalesced loaders, double-buffered dynamic smem.
// ---------------------------------------------------------------------------
#define G1_SMEM_BYTES 101376
__global__ __launch_bounds__(256, 1) void gemm1_kernel(const float* __restrict__ x,
                                                       const float* __restrict__ W1,
                                                       const float* __restrict__ W3) {
    extern __shared__ uint32_t dsm[];
    int*      stok = reinterpret_cast<int*>(dsm);      // 256
    uint32_t* Asb  = dsm + 256;                        // 2 x 8192
    uint32_t* B1b  = dsm + 256 + 16384;                // 2 x 2176
    uint32_t* B3b  = dsm + 256 + 16384 + 4352;         // 2 x 2176

    const int e   = blockIdx.y >> 5;
    const int mt  = blockIdx.y & 31;
    const int cnt = g_count[e];
    const int m0  = mt * 256;
    if (m0 >= cnt) return;
    const int n0 = blockIdx.x * 64;

    const int tid  = threadIdx.x;
    const int warp = tid >> 5;
    const int lane = tid & 31;
    const int wm = warp >> 1;
    const int wn = warp & 1;
    const int g  = lane >> 2;
    const int t  = lane & 3;

    // A loader: pass p covers rows p*32 + (tid>>3); 8 lanes per row (coalesced)
    const int rsub = tid >> 3;
    const int csub = (tid & 7) * 4;
    // B loader: pair-row pr = tid>>4 (k = (pr>>2)*8 + (pr&3)); cols nb+16j
    const int pr = tid >> 4;
    const int nb = tid & 15;
    const int kk = (pr >> 2) * 8 + (pr & 3);

    {
        const int m = m0 + tid;
        stok[tid] = (m < cnt) ? g_rows[e * TOK + m] : g_rows[e * TOK];
    }
    __syncthreads();
    int tokp[8];
#pragma unroll
    for (int p = 0; p < 8; p++) tokp[p] = stok[p * 32 + rsub];

    const float* pB1 = W1 + (size_t)e * DDIM * FDIM + n0;
    const float* pB3 = W3 + (size_t)e * DDIM * FDIM + n0;

    float acc1[4][4][4], acc3[4][4][4];
#pragma unroll
    for (int i = 0; i < 4; i++)
#pragma unroll
        for (int j = 0; j < 4; j++)
#pragma unroll
            for (int r = 0; r < 4; r++) { acc1[i][j][r] = 0.f; acc3[i][j][r] = 0.f; }

    float4 aq[8];
    float b1lo[4], b1hi[4], b3lo[4], b3hi[4];

    auto ldg_chunk = [&](int k0) {
#pragma unroll
        for (int p = 0; p < 8; p++)
            aq[p] = *reinterpret_cast<const float4*>(
                x + (size_t)tokp[p] * DDIM + k0 + csub);
        const float* r1a = pB1 + (size_t)(k0 + kk) * FDIM;
        const float* r1b = pB1 + (size_t)(k0 + kk + 4) * FDIM;
        const float* r3a = pB3 + (size_t)(k0 + kk) * FDIM;
        const float* r3b = pB3 + (size_t)(k0 + kk + 4) * FDIM;
#pragma unroll
        for (int j = 0; j < 4; j++) {
            b1lo[j] = r1a[nb + 16 * j]; b1hi[j] = r1b[nb + 16 * j];
            b3lo[j] = r3a[nb + 16 * j]; b3hi[j] = r3b[nb + 16 * j];
        }
    };
    auto sts_chunk = [&](int buf) {
        uint32_t* A  = Asb + buf * 8192;
        uint32_t* B1 = B1b + buf * 2176;
        uint32_t* B3 = B3b + buf * 2176;
#pragma unroll
        for (int p = 0; p < 8; p++) {
            const int row = p * 32 + rsub;
            a_store(A, row, csub + 0, aq[p].x);
            a_store(A, row, csub + 1, aq[p].y);
            a_store(A, row, csub + 2, aq[p].z);
            a_store(A, row, csub + 3, aq[p].w);
        }
#pragma unroll
        for (int j = 0; j < 4; j++) {
            *reinterpret_cast<uint2*>(&B1[(pr * PBS1 + nb + 16 * j) * 2]) =
                make_uint2(f2tf32(b1lo[j]), f2tf32(b1hi[j]));
            *reinterpret_cast<uint2*>(&B3[(pr * PBS1 + nb + 16 * j) * 2]) =
                make_uint2(f2tf32(b3lo[j]), f2tf32(b3hi[j]));
        }
    };

    ldg_chunk(0);
    sts_chunk(0);
    __syncthreads();

    const int NCH = DDIM / BK;  // 32
    for (int c = 0; c < NCH; c++) {
        const int p = c & 1;
        if (c + 1 < NCH) ldg_chunk((c + 1) * BK);

        uint32_t* A  = Asb + p * 8192;
        uint32_t* B1 = B1b + p * 2176;
        uint32_t* B3 = B3b + p * 2176;
#pragma unroll
        for (int ks = 0; ks < 4; ks++) {
            uint4 af[4];
#pragma unroll
            for (int i = 0; i < 4; i++)
                af[i] = *reinterpret_cast<const uint4*>(&A[a_off(wm * 4 + i, ks, lane, 0)]);
#pragma unroll
            for (int j = 0; j < 4; j++) {
                const int col = wn * 32 + j * 8 + g;
                const uint2 p1 = *reinterpret_cast<const uint2*>(
                    &B1[((ks * 4 + t) * PBS1 + col) * 2]);
                const uint2 p3 = *reinterpret_cast<const uint2*>(
                    &B3[((ks * 4 + t) * PBS1 + col) * 2]);
#pragma unroll
                for (int i = 0; i < 4; i++) {
                    mma4(acc1[i][j], af[i], p1.x, p1.y);
                    mma4(acc3[i][j], af[i], p3.x, p3.y);
                }
            }
        }

        if (c + 1 < NCH) {
            sts_chunk(p ^ 1);
            __syncthreads();
        }
    }

    float* Hbase = g_H + (size_t)e * TOK * FDIM;
    const int lim = cnt - m0;
#pragma unroll
    for (int i = 0; i < 4; i++) {
        const int lrow0 = wm * 64 + i * 16 + g;
        const int lrow1 = lrow0 + 8;
#pragma unroll
        for (int j = 0; j < 4; j++) {
            const int col = n0 + wn * 32 + j * 8 + 2 * t;
            if (lrow0 < lim) {
                const float z0 = acc1[i][j][0], z1 = acc1[i][j][1];
                float2 hv;
                hv.x = (z0 / (1.f + expf(-z0))) * acc3[i][j][0];
                hv.y = (z1 / (1.f + expf(-z1))) * acc3[i][j][1];
                *reinterpret_cast<float2*>(Hbase + (size_t)(m0 + lrow0) * FDIM + col) = hv;
            }
            if (lrow1 < lim) {
                const float z2 = acc1[i][j][2], z3 = acc1[i][j][3];
                float2 hv;
                hv.x = (z2 / (1.f + expf(-z2))) * acc3[i][j][2];
                hv.y = (z3 / (1.f + expf(-z3))) * acc3[i][j][3];
                *reinterpret_cast<float2*>(Hbase + (size_t)(m0 + lrow1) * FDIM + col) = hv;
            }
        }
    }
}

// ---------------------------------------------------------------------------
// 3) Grouped GEMM2. Block 256x128, 8 warps (4m x 2n), warp 64x64. BK=32.
// ---------------------------------------------------------------------------
#define G2_SMEM_BYTES 99328
__global__ __launch_bounds__(256, 1) void gemm2_kernel(const float* __restrict__ W2) {
    extern __shared__ uint32_t dsm[];
    uint32_t* Asb = dsm;            // 2 x 8192
    uint32_t* Bb  = dsm + 16384;    // 2 x 4224

    const int e   = blockIdx.y >> 5;
    const int mt  = blockIdx.y & 31;
    const int cnt = g_count[e];
    const int m0  = mt * 256;
    if (m0 >= cnt) return;
    const int n0 = blockIdx.x * 128;

    const int tid  = threadIdx.x;
    const int warp = tid >> 5;
    const int lane = tid & 31;
    const int wm = warp >> 1;
    const int wn = warp & 1;
    const int g  = lane >> 2;
    const int t  = lane & 3;

    const int rsub = tid >> 3;
    const int csub = (tid & 7) * 4;
    const int pr = tid >> 4;
    const int nb = tid & 15;
    const int kk = (pr >> 2) * 8 + (pr & 3);

    const float* Hbase = g_H + ((size_t)e * TOK + m0) * FDIM;
    const float* pB = W2 + (size_t)e * FDIM * DDIM + n0;

    float acc[4][8][4];
#pragma unroll
    for (int i = 0; i < 4; i++)
#pragma unroll
        for (int j = 0; j < 8; j++)
#pragma unroll
            for (int r = 0; r < 4; r++) acc[i][j][r] = 0.f;

    float4 aq[8];
    float blo[8], bhi[8];

    auto ldg_chunk = [&](int k0) {
#pragma unroll
        for (int p = 0; p < 8; p++)
            aq[p] = *reinterpret_cast<const float4*>(
                Hbase + (size_t)(p * 32 + rsub) * FDIM + k0 + csub);
        const float* ra = pB + (size_t)(k0 + kk) * DDIM;
        const float* rb = pB + (size_t)(k0 + kk + 4) * DDIM;
#pragma unroll
        for (int j = 0; j < 8; j++) {
            blo[j] = ra[nb + 16 * j];
            bhi[j] = rb[nb + 16 * j];
        }
    };
    auto sts_chunk = [&](int buf) {
        uint32_t* A = Asb + buf * 8192;
        uint32_t* B = Bb  + buf * 4224;
#pragma unroll
        for (int p = 0; p < 8; p++) {
            const int row = p * 32 + rsub;
            a_store(A, row, csub + 0, aq[p].x);
            a_store(A, row, csub + 1, aq[p].y);
            a_store(A, row, csub + 2, aq[p].z);
            a_store(A, row, csub + 3, aq[p].w);
        }
#pragma unroll
        for (int j = 0; j < 8; j++)
            *reinterpret_cast<uint2*>(&B[(pr * PBS2 + nb + 16 * j) * 2]) =
                make_uint2(f2tf32(blo[j]), f2tf32(bhi[j]));
    };

    ldg_chunk(0);
    sts_chunk(0);
    __syncthreads();

    const int NCH = FDIM / BK;  // 64
    for (int c = 0; c < NCH; c++) {
        const int p = c & 1;
        if (c + 1 < NCH) ldg_chunk((c + 1) * BK);

        uint32_t* A = Asb + p * 8192;
        uint32_t* B = Bb  + p * 4224;
#pragma unroll
        for (int ks = 0; ks < 4; ks++) {
            uint4 af[4];
#pragma unroll
            for (int i = 0; i < 4; i++)
                af[i] = *reinterpret_cast<const uint4*>(&A[a_off(wm * 4 + i, ks, lane, 0)]);
#pragma unroll
            for (int j = 0; j < 8; j++) {
                const int col = wn * 64 + j * 8 + g;
                const uint2 prb = *reinterpret_cast<const uint2*>(
                    &B[((ks * 4 + t) * PBS2 + col) * 2]);
#pragma unroll
                for (int i = 0; i < 4; i++)
                    mma4(acc[i][j], af[i], prb.x, prb.y);
            }
        }

        if (c + 1 < NCH) {
            sts_chunk(p ^ 1);
            __syncthreads();
        }
    }

    const int lim = cnt - m0;
#pragma unroll
    for (int i = 0; i < 4; i++) {
        const int lrow0 = wm * 64 + i * 16 + g;
        const int lrow1 = lrow0 + 8;
        const int slot0 = (lrow0 < lim) ? g_slot[e * TOK + m0 + lrow0] : -1;
        const int slot1 = (lrow1 < lim) ? g_slot[e * TOK + m0 + lrow1] : -1;
#pragma unroll
        for (int j = 0; j < 8; j++) {
            const int col = n0 + wn * 64 + j * 8 + 2 * t;
            if (slot0 >= 0)
                *reinterpret_cast<float2*>(g_Y + (size_t)slot0 * DDIM + col) =
                    make_float2(acc[i][j][0], acc[i][j][1]);
            if (slot1 >= 0)
                *reinterpret_cast<float2*>(g_Y + (size_t)slot1 * DDIM + col) =
                    make_float2(acc[i][j][2], acc[i][j][3]);
        }
    }
}

// ---------------------------------------------------------------------------
// 4) Combine
// ---------------------------------------------------------------------------
__global__ __launch_bounds__(256) void combine_kernel(float* __restrict__ out) {
    const int tk = blockIdx.x;
    const int d = threadIdx.x * 4;
    const float g0 = g_gate[tk * 2 + 0];
    const float g1 = g_gate[tk * 2 + 1];
    const float4 y0 = *reinterpret_cast<const float4*>(g_Y + ((size_t)tk * 2 + 0) * DDIM + d);
    const float4 y1 = *reinterpret_cast<const float4*>(g_Y + ((size_t)tk * 2 + 1) * DDIM + d);
    float4 o;
    o.x = g0 * y0.x + g1 * y1.x;
    o.y = g0 * y0.y + g1 * y1.y;
    o.z = g0 * y0.z + g1 * y1.z;
    o.w = g0 * y0.w + g1 * y1.w;
    *reinterpret_cast<float4*>(out + (size_t)tk * DDIM + d) = o;
}

// ---------------------------------------------------------------------------
// Entry
// ---------------------------------------------------------------------------
extern "C" void kernel_launch(void* const* d_in, const int* in_sizes, int n_in,
                              void* d_out, int out_size) {
    const float* x  = (const float*)d_in[0];
    const float* Wg = (const float*)d_in[1];
    const float* W1 = (const float*)d_in[2];
    const float* W3 = (const float*)d_in[3];
    const float* W2 = (const float*)d_in[4];
    float* out = (float*)d_out;

    static int attr_done = 0;
    if (!attr_done) {
        cudaFuncSetAttribute(gemm1_kernel,
                             cudaFuncAttributeMaxDynamicSharedMemorySize, G1_SMEM_BYTES);
        cudaFuncSetAttribute(gemm2_kernel,
                             cudaFuncAttributeMaxDynamicSharedMemorySize, G2_SMEM_BYTES);
        attr_done = 1;
    }

    zero_counts_kernel<<<1, 32>>>();
    router_kernel<<<TOK / 8, 256>>>(x, Wg);
    gemm1_kernel<<<dim3(FDIM / 64, NEXP * (TOK / 256)), 256, G1_SMEM_BYTES>>>(x, W1, W3);
    gemm2_kernel<<<dim3(DDIM / 128, NEXP * (TOK / 256)), 256, G2_SMEM_BYTES>>>(W2);
    combine_kernel<<<TOK, 256>>>(out);
}

// round 11
// speedup vs baseline: 2.4399x; 1.1714x over previous
#include <cuda_runtime.h>
#include <math.h>
#include <stdint.h>

// Problem constants
#define TOK   8192
#define DDIM  1024
#define FDIM  2048
#define NEXP  8
#define TOPK  2

#define BK    32
#define NW4   ((size_t)NEXP * DDIM * FDIM / 4)
#define NX4   ((size_t)TOK * DDIM / 4)

// ---------------------------------------------------------------------------
// Scratch
// ---------------------------------------------------------------------------
__device__ int   g_count[NEXP];
__device__ int   g_rows [NEXP * TOK];
__device__ int   g_slot [NEXP * TOK];
__device__ float g_gate [TOK * TOPK];
__device__ __align__(16) float g_H  [(size_t)NEXP * TOK * FDIM];
__device__ __align__(16) float g_Y  [(size_t)TOK * TOPK * DDIM];
// tf32-pre-rounded copies
__device__ __align__(16) float g_X  [(size_t)TOK * DDIM];
__device__ __align__(16) float g_W1r[(size_t)NEXP * DDIM * FDIM];
__device__ __align__(16) float g_W3r[(size_t)NEXP * DDIM * FDIM];
__device__ __align__(16) float g_W2r[(size_t)NEXP * FDIM * DDIM];

// ---------------------------------------------------------------------------
// helpers
// ---------------------------------------------------------------------------
__device__ __forceinline__ uint32_t f2tf32(float f) {
    uint32_t u;
    asm("cvt.rna.tf32.f32 %0, %1;" : "=r"(u) : "f"(f));
    return u;
}

__device__ __forceinline__ void mma4(float c[4], const uint4& a,
                                     uint32_t b0, uint32_t b1) {
    asm volatile(
        "mma.sync.aligned.m16n8k8.row.col.f32.tf32.tf32.f32 "
        "{%0,%1,%2,%3}, {%4,%5,%6,%7}, {%8,%9}, {%0,%1,%2,%3};"
        : "+f"(c[0]), "+f"(c[1]), "+f"(c[2]), "+f"(c[3])
        : "r"(a.x), "r"(a.y), "r"(a.z), "r"(a.w), "r"(b0), "r"(b1));
}

__device__ __forceinline__ uint32_t smem_u32(const void* p) {
    uint32_t a;
    asm("{ .reg .u64 t; cvta.to.shared.u64 t, %1; cvt.u32.u64 %0, t; }"
        : "=r"(a) : "l"(p));
    return a;
}

#define CP16(dst, src) \
    asm volatile("cp.async.cg.shared.global [%0], [%1], 16;" \
                 :: "r"(dst), "l"(src) : "memory")
#define CPCOMMIT() asm volatile("cp.async.commit_group;" ::: "memory")
#define CPWAIT1()  asm volatile("cp.async.wait_group 1;" ::: "memory")
#define CPWAIT0()  asm volatile("cp.async.wait_group 0;" ::: "memory")

// ---------------------------------------------------------------------------
// 0) zero expert counters
// ---------------------------------------------------------------------------
__global__ void zero_counts_kernel() {
    if (threadIdx.x < NEXP) g_count[threadIdx.x] = 0;
}

// ---------------------------------------------------------------------------
// 0b) Pre-round inputs to tf32 (rna) so HMMA truncation is exact.
// ---------------------------------------------------------------------------
__global__ __launch_bounds__(256) void prep_kernel(const float4* __restrict__ x,
                                                   const float4* __restrict__ W1,
                                                   const float4* __restrict__ W3,
                                                   const float4* __restrict__ W2) {
    const size_t total = NX4 + 3 * NW4;
    const size_t stride = (size_t)gridDim.x * 256;
    for (size_t i = (size_t)blockIdx.x * 256 + threadIdx.x; i < total; i += stride) {
        const float4* src; float4* dst; size_t off;
        if (i < NX4)            { src = x;  dst = (float4*)g_X;   off = i; }
        else if (i < NX4 + NW4) { src = W1; dst = (float4*)g_W1r; off = i - NX4; }
        else if (i < NX4 + 2 * NW4) { src = W3; dst = (float4*)g_W3r; off = i - NX4 - NW4; }
        else                    { src = W2; dst = (float4*)g_W2r; off = i - NX4 - 2 * NW4; }
        float4 v = src[off];
        uint4 w = make_uint4(f2tf32(v.x), f2tf32(v.y), f2tf32(v.z), f2tf32(v.w));
        dst[off] = *reinterpret_cast<float4*>(&w);
    }
}

// ---------------------------------------------------------------------------
// 1) Router (one warp per token)
// ---------------------------------------------------------------------------
__global__ __launch_bounds__(256) void router_kernel(const float* __restrict__ x,
                                                     const float* __restrict__ Wg) {
    const int warp = (blockIdx.x * blockDim.x + threadIdx.x) >> 5;
    const int lane = threadIdx.x & 31;
    if (warp >= TOK) return;

    const float* xr = x + (size_t)warp * DDIM;
    float acc[NEXP];
#pragma unroll
    for (int e = 0; e < NEXP; e++) acc[e] = 0.f;

    for (int d = lane; d < DDIM; d += 32) {
        const float xv = xr[d];
        const float4 w0 = *reinterpret_cast<const float4*>(Wg + (size_t)d * NEXP);
        const float4 w1 = *reinterpret_cast<const float4*>(Wg + (size_t)d * NEXP + 4);
        acc[0] += xv * w0.x; acc[1] += xv * w0.y; acc[2] += xv * w0.z; acc[3] += xv * w0.w;
        acc[4] += xv * w1.x; acc[5] += xv * w1.y; acc[6] += xv * w1.z; acc[7] += xv * w1.w;
    }
#pragma unroll
    for (int off = 16; off > 0; off >>= 1) {
#pragma unroll
        for (int e = 0; e < NEXP; e++)
            acc[e] += __shfl_xor_sync(0xFFFFFFFFu, acc[e], off);
    }

    if (lane == 0) {
        int i0 = 0; float v0 = acc[0];
#pragma unroll
        for (int e = 1; e < NEXP; e++) if (acc[e] > v0) { v0 = acc[e]; i0 = e; }
        int i1 = -1; float v1 = -INFINITY;
#pragma unroll
        for (int e = 0; e < NEXP; e++)
            if (e != i0 && acc[e] > v1) { v1 = acc[e]; i1 = e; }

        const float e1 = expf(v1 - v0);
        const float inv = 1.f / (1.f + e1);
        g_gate[warp * 2 + 0] = inv;
        g_gate[warp * 2 + 1] = e1 * inv;

        int p0 = atomicAdd(&g_count[i0], 1);
        g_rows[i0 * TOK + p0] = warp;
        g_slot[i0 * TOK + p0] = warp * 2;
        int p1 = atomicAdd(&g_count[i1], 1);
        g_rows[i1 * TOK + p1] = warp;
        g_slot[i1 * TOK + p1] = warp * 2 + 1;
    }
}

// ---------------------------------------------------------------------------
// 2) Grouped dual GEMM + SwiGLU. Block 256x64 dual, 8 warps (4m x 2n),
//    warp 64x32 dual. cp.async 3-stage pipeline.
// Smem layout per stage (uint32 idx): A[256][32] swizzled @0, B1[32][64] @8192,
// B3[32][64] @10240. Stage size 12288 u32 = 49152 B.
// ---------------------------------------------------------------------------
#define G1_SMEM_BYTES (1024 + 3 * 49152)
__global__ __launch_bounds__(256, 1) void gemm1_kernel() {
    extern __shared__ uint32_t dsm[];
    int*      stok = reinterpret_cast<int*>(dsm);
    uint32_t* stg  = dsm + 256;

    const int e   = blockIdx.y >> 5;
    const int mt  = blockIdx.y & 31;
    const int cnt = g_count[e];
    const int m0  = mt * 256;
    if (m0 >= cnt) return;
    const int n0 = blockIdx.x * 64;

    const int tid  = threadIdx.x;
    const int warp = tid >> 5;
    const int lane = tid & 31;
    const int wm = warp >> 1;
    const int wn = warp & 1;
    const int g  = lane >> 2;
    const int t  = lane & 3;

    // loader indices
    const int rsub = tid >> 3;                 // 0..31
    const int kq   = (tid & 7) * 4;            // 0..28
    const int adk  = kq ^ ((rsub & 7) << 2);   // swizzled k within row
    const int bkr  = tid >> 4;                 // 0..15
    const int bnq  = (tid & 15) * 4;           // 0..60

    {
        const int m = m0 + tid;
        stok[tid] = (m < cnt) ? g_rows[e * TOK + m] : g_rows[e * TOK];
    }
    __syncthreads();
    int tokp[8];
#pragma unroll
    for (int p = 0; p < 8; p++) tokp[p] = stok[p * 32 + rsub];

    const float* W1e = g_W1r + (size_t)e * DDIM * FDIM + n0;
    const float* W3e = g_W3r + (size_t)e * DDIM * FDIM + n0;
    const uint32_t sb = smem_u32(dsm) + 1024;

    float acc1[4][4][4], acc3[4][4][4];
#pragma unroll
    for (int i = 0; i < 4; i++)
#pragma unroll
        for (int j = 0; j < 4; j++)
#pragma unroll
            for (int r = 0; r < 4; r++) { acc1[i][j][r] = 0.f; acc3[i][j][r] = 0.f; }

    auto issue = [&](int s, int k0) {
        const uint32_t base = sb + s * 49152;
#pragma unroll
        for (int p = 0; p < 8; p++) {
            const float* src = g_X + (size_t)tokp[p] * DDIM + k0 + kq;
            CP16(base + (uint32_t)(((p * 32 + rsub) * 32 + adk) * 4), src);
        }
#pragma unroll
        for (int i = 0; i < 2; i++) {
            const int k  = i * 16 + bkr;
            const int dn = bnq ^ ((k & 3) << 3);
            CP16(base + 32768u + (uint32_t)((k * 64 + dn) * 4),
                 W1e + (size_t)(k0 + k) * FDIM + bnq);
            CP16(base + 40960u + (uint32_t)((k * 64 + dn) * 4),
                 W3e + (size_t)(k0 + k) * FDIM + bnq);
        }
        CPCOMMIT();
    };

    issue(0, 0);
    issue(1, BK);

    const int NCH = DDIM / BK;  // 32
    for (int c = 0; c < NCH; c++) {
        if (c + 1 < NCH) { CPWAIT1(); } else { CPWAIT0(); }
        __syncthreads();
        if (c + 2 < NCH) issue((c + 2) % 3, (c + 2) * BK);

        const uint32_t* A  = stg + (c % 3) * 12288;
        const uint32_t* B1 = A + 8192;
        const uint32_t* B3 = A + 10240;
#pragma unroll
        for (int ks = 0; ks < 4; ks++) {
            const int kL = ks * 8 + t, kH = kL + 4;
            const int axL = kL ^ (g << 2), axH = kH ^ (g << 2);
            uint4 af[4];
#pragma unroll
            for (int i = 0; i < 4; i++) {
                const int rL = (wm * 4 + i) * 16 + g;
                af[i].x = A[rL * 32 + axL];
                af[i].y = A[(rL + 8) * 32 + axL];
                af[i].z = A[rL * 32 + axH];
                af[i].w = A[(rL + 8) * 32 + axH];
            }
#pragma unroll
            for (int j = 0; j < 4; j++) {
                const int cx = (wn * 32 + j * 8 + g) ^ (t << 3);
                const uint32_t b10 = B1[kL * 64 + cx], b11 = B1[kH * 64 + cx];
                const uint32_t b30 = B3[kL * 64 + cx], b31 = B3[kH * 64 + cx];
#pragma unroll
                for (int i = 0; i < 4; i++) {
                    mma4(acc1[i][j], af[i], b10, b11);
                    mma4(acc3[i][j], af[i], b30, b31);
                }
            }
        }
    }

    // Epilogue: fused SiLU*up, rounded to tf32 so gemm2's HMMA truncation is exact.
    float* Hbase = g_H + (size_t)e * TOK * FDIM;
    const int lim = cnt - m0;
#pragma unroll
    for (int i = 0; i < 4; i++) {
        const int lrow0 = wm * 64 + i * 16 + g;
        const int lrow1 = lrow0 + 8;
#pragma unroll
        for (int j = 0; j < 4; j++) {
            const int col = n0 + wn * 32 + j * 8 + 2 * t;
            if (lrow0 < lim) {
                const float z0 = acc1[i][j][0], z1 = acc1[i][j][1];
                float2 hv;
                hv.x = __uint_as_float(f2tf32((z0 / (1.f + expf(-z0))) * acc3[i][j][0]));
                hv.y = __uint_as_float(f2tf32((z1 / (1.f + expf(-z1))) * acc3[i][j][1]));
                *reinterpret_cast<float2*>(Hbase + (size_t)(m0 + lrow0) * FDIM + col) = hv;
            }
            if (lrow1 < lim) {
                const float z2 = acc1[i][j][2], z3 = acc1[i][j][3];
                float2 hv;
                hv.x = __uint_as_float(f2tf32((z2 / (1.f + expf(-z2))) * acc3[i][j][2]));
                hv.y = __uint_as_float(f2tf32((z3 / (1.f + expf(-z3))) * acc3[i][j][3]));
                *reinterpret_cast<float2*>(Hbase + (size_t)(m0 + lrow1) * FDIM + col) = hv;
            }
        }
    }
}

// ---------------------------------------------------------------------------
// 3) Grouped GEMM2. Block 256x128, 8 warps (4m x 2n), warp 64x64.
// Smem per stage: A[256][32] @0 (8192 u32), B[32][128] @8192 (4096 u32).
// ---------------------------------------------------------------------------
#define G2_SMEM_BYTES (3 * 49152)
__global__ __launch_bounds__(256, 1) void gemm2_kernel() {
    extern __shared__ uint32_t dsm[];
    uint32_t* stg = dsm;

    const int e   = blockIdx.y >> 5;
    const int mt  = blockIdx.y & 31;
    const int cnt = g_count[e];
    const int m0  = mt * 256;
    if (m0 >= cnt) return;
    const int n0 = blockIdx.x * 128;

    const int tid  = threadIdx.x;
    const int warp = tid >> 5;
    const int lane = tid & 31;
    const int wm = warp >> 1;
    const int wn = warp & 1;
    const int g  = lane >> 2;
    const int t  = lane & 3;

    const int rsub = tid >> 3;
    const int kq   = (tid & 7) * 4;
    const int adk  = kq ^ ((rsub & 7) << 2);
    const int bkr  = tid >> 5;                 // 0..7
    const int bnq2 = (tid & 31) * 4;           // 0..124

    const float* Hbase = g_H + ((size_t)e * TOK + m0) * FDIM;
    const float* W2e   = g_W2r + (size_t)e * FDIM * DDIM + n0;
    const uint32_t sb = smem_u32(dsm);

    float acc[4][8][4];
#pragma unroll
    for (int i = 0; i < 4; i++)
#pragma unroll
        for (int j = 0; j < 8; j++)
#pragma unroll
            for (int r = 0; r < 4; r++) acc[i][j][r] = 0.f;

    auto issue = [&](int s, int k0) {
        const uint32_t base = sb + s * 49152;
#pragma unroll
        for (int p = 0; p < 8; p++) {
            const int row = p * 32 + rsub;
            const float* src = Hbase + (size_t)row * FDIM + k0 + kq;
            CP16(base + (uint32_t)((row * 32 + adk) * 4), src);
        }
#pragma unroll
        for (int i = 0; i < 4; i++) {
            const int k  = i * 8 + bkr;
            const int dn = bnq2 ^ ((k & 3) << 3);
            CP16(base + 32768u + (uint32_t)((k * 128 + dn) * 4),
                 W2e + (size_t)(k0 + k) * DDIM + bnq2);
        }
        CPCOMMIT();
    };

    issue(0, 0);
    issue(1, BK);

    const int NCH = FDIM / BK;  // 64
    for (int c = 0; c < NCH; c++) {
        if (c + 1 < NCH) { CPWAIT1(); } else { CPWAIT0(); }
        __syncthreads();
        if (c + 2 < NCH) issue((c + 2) % 3, (c + 2) * BK);

        const uint32_t* A = stg + (c % 3) * 12288;
        const uint32_t* B = A + 8192;
#pragma unroll
        for (int ks = 0; ks < 4; ks++) {
            const int kL = ks * 8 + t, kH = kL + 4;
            const int axL = kL ^ (g << 2), axH = kH ^ (g << 2);
            uint4 af[4];
#pragma unroll
            for (int i = 0; i < 4; i++) {
                const int rL = (wm * 4 + i) * 16 + g;
                af[i].x = A[rL * 32 + axL];
                af[i].y = A[(rL + 8) * 32 + axL];
                af[i].z = A[rL * 32 + axH];
                af[i].w = A[(rL + 8) * 32 + axH];
            }
#pragma unroll
            for (int j = 0; j < 8; j++) {
                const int cx = (wn * 64 + j * 8 + g) ^ (t << 3);
                const uint32_t b0 = B[kL * 128 + cx], b1 = B[kH * 128 + cx];
#pragma unroll
                for (int i = 0; i < 4; i++)
                    mma4(acc[i][j], af[i], b0, b1);
            }
        }
    }

    const int lim = cnt - m0;
#pragma unroll
    for (int i = 0; i < 4; i++) {
        const int lrow0 = wm * 64 + i * 16 + g;
        const int lrow1 = lrow0 + 8;
        const int slot0 = (lrow0 < lim) ? g_slot[e * TOK + m0 + lrow0] : -1;
        const int slot1 = (lrow1 < lim) ? g_slot[e * TOK + m0 + lrow1] : -1;
#pragma unroll
        for (int j = 0; j < 8; j++) {
            const int col = n0 + wn * 64 + j * 8 + 2 * t;
            if (slot0 >= 0)
                *reinterpret_cast<float2*>(g_Y + (size_t)slot0 * DDIM + col) =
                    make_float2(acc[i][j][0], acc[i][j][1]);
            if (slot1 >= 0)
                *reinterpret_cast<float2*>(g_Y + (size_t)slot1 * DDIM + col) =
                    make_float2(acc[i][j][2], acc[i][j][3]);
        }
    }
}

// ---------------------------------------------------------------------------
// 4) Combine
// ---------------------------------------------------------------------------
__global__ __launch_bounds__(256) void combine_kernel(float* __restrict__ out) {
    const int tk = blockIdx.x;
    const int d = threadIdx.x * 4;
    const float g0 = g_gate[tk * 2 + 0];
    const float g1 = g_gate[tk * 2 + 1];
    const float4 y0 = *reinterpret_cast<const float4*>(g_Y + ((size_t)tk * 2 + 0) * DDIM + d);
    const float4 y1 = *reinterpret_cast<const float4*>(g_Y + ((size_t)tk * 2 + 1) * DDIM + d);
    float4 o;
    o.x = g0 * y0.x + g1 * y1.x;
    o.y = g0 * y0.y + g1 * y1.y;
    o.z = g0 * y0.z + g1 * y1.z;
    o.w = g0 * y0.w + g1 * y1.w;
    *reinterpret_cast<float4*>(out + (size_t)tk * DDIM + d) = o;
}

// ---------------------------------------------------------------------------
// Entry
// ---------------------------------------------------------------------------
extern "C" void kernel_launch(void* const* d_in, const int* in_sizes, int n_in,
                              void* d_out, int out_size) {
    const float* x  = (const float*)d_in[0];
    const float* Wg = (const float*)d_in[1];
    const float* W1 = (const float*)d_in[2];
    const float* W3 = (const float*)d_in[3];
    const float* W2 = (const float*)d_in[4];
    float* out = (float*)d_out;

    static int attr_done = 0;
    if (!attr_done) {
        cudaFuncSetAttribute(gemm1_kernel,
                             cudaFuncAttributeMaxDynamicSharedMemorySize, G1_SMEM_BYTES);
        cudaFuncSetAttribute(gemm2_kernel,
                             cudaFuncAttributeMaxDynamicSharedMemorySize, G2_SMEM_BYTES);
        attr_done = 1;
    }

    zero_counts_kernel<<<1, 32>>>();
    prep_kernel<<<4096, 256>>>((const float4*)x, (const float4*)W1,
                               (const float4*)W3, (const float4*)W2);
    router_kernel<<<TOK / 8, 256>>>(x, Wg);
    gemm1_kernel<<<dim3(FDIM / 64, NEXP * (TOK / 256)), 256, G1_SMEM_BYTES>>>();
    gemm2_kernel<<<dim3(DDIM / 128, NEXP * (TOK / 256)), 256, G2_SMEM_BYTES>>>();
    combine_kernel<<<TOK, 256>>>(out);
}

// round 12
// speedup vs baseline: 3.9505x; 1.6192x over previous
#include <cuda_runtime.h>
#include <cuda_fp16.h>
#include <math.h>
#include <stdint.h>

// Problem constants
#define TOK   8192
#define DDIM  1024
#define FDIM  2048
#define NEXP  8
#define TOPK  2

#define BK    32
#define NW4   ((size_t)NEXP * DDIM * FDIM / 4)
#define NX4   ((size_t)TOK * DDIM / 4)

// ---------------------------------------------------------------------------
// Scratch
// ---------------------------------------------------------------------------
__device__ int   g_count[NEXP];
__device__ int   g_rows [NEXP * TOK];
__device__ int   g_slot [NEXP * TOK];
__device__ float g_gate [TOK * TOPK];
__device__ __align__(16) float  g_Y  [(size_t)TOK * TOPK * DDIM];
// fp16 copies / intermediates
__device__ __align__(16) __half g_X  [(size_t)TOK * DDIM];
__device__ __align__(16) __half g_W1h[(size_t)NEXP * DDIM * FDIM];
__device__ __align__(16) __half g_W3h[(size_t)NEXP * DDIM * FDIM];
__device__ __align__(16) __half g_W2h[(size_t)NEXP * FDIM * DDIM];
__device__ __align__(16) __half g_Hh [(size_t)NEXP * TOK * FDIM];

// ---------------------------------------------------------------------------
// helpers
// ---------------------------------------------------------------------------
__device__ __forceinline__ uint32_t smem_u32(const void* p) {
    uint32_t a;
    asm("{ .reg .u64 t; cvta.to.shared.u64 t, %1; cvt.u32.u64 %0, t; }"
        : "=r"(a) : "l"(p));
    return a;
}

__device__ __forceinline__ void mmah(float c[4], const uint32_t a[4],
                                     uint32_t b0, uint32_t b1) {
    asm volatile(
        "mma.sync.aligned.m16n8k16.row.col.f32.f16.f16.f32 "
        "{%0,%1,%2,%3}, {%4,%5,%6,%7}, {%8,%9}, {%0,%1,%2,%3};"
        : "+f"(c[0]), "+f"(c[1]), "+f"(c[2]), "+f"(c[3])
        : "r"(a[0]), "r"(a[1]), "r"(a[2]), "r"(a[3]), "r"(b0), "r"(b1));
}

__device__ __forceinline__ void ldsm4(uint32_t r[4], uint32_t addr) {
    asm volatile("ldmatrix.sync.aligned.m8n8.x4.shared.b16 {%0,%1,%2,%3}, [%4];"
                 : "=r"(r[0]), "=r"(r[1]), "=r"(r[2]), "=r"(r[3]) : "r"(addr));
}

__device__ __forceinline__ void ldsm4t(uint32_t r[4], uint32_t addr) {
    asm volatile("ldmatrix.sync.aligned.m8n8.x4.trans.shared.b16 {%0,%1,%2,%3}, [%4];"
                 : "=r"(r[0]), "=r"(r[1]), "=r"(r[2]), "=r"(r[3]) : "r"(addr));
}

#define CP16(dst, src) \
    asm volatile("cp.async.cg.shared.global [%0], [%1], 16;" \
                 :: "r"(dst), "l"(src) : "memory")
#define CPCOMMIT() asm volatile("cp.async.commit_group;" ::: "memory")
#define CPWAIT2()  asm volatile("cp.async.wait_group 2;" ::: "memory")

// ---------------------------------------------------------------------------
// 0) zero expert counters
// ---------------------------------------------------------------------------
__global__ void zero_counts_kernel() {
    if (threadIdx.x < NEXP) g_count[threadIdx.x] = 0;
}

// ---------------------------------------------------------------------------
// 0b) Convert x, W1, W3, W2 to fp16 copies.
// ---------------------------------------------------------------------------
__global__ __launch_bounds__(256) void prep_kernel(const float4* __restrict__ x,
                                                   const float4* __restrict__ W1,
                                                   const float4* __restrict__ W3,
                                                   const float4* __restrict__ W2) {
    const size_t total = NX4 + 3 * NW4;
    const size_t stride = (size_t)gridDim.x * 256;
    for (size_t i = (size_t)blockIdx.x * 256 + threadIdx.x; i < total; i += stride) {
        const float4* src; __half2* dst; size_t off;
        if (i < NX4)                { src = x;  dst = (__half2*)g_X;   off = i; }
        else if (i < NX4 + NW4)     { src = W1; dst = (__half2*)g_W1h; off = i - NX4; }
        else if (i < NX4 + 2 * NW4) { src = W3; dst = (__half2*)g_W3h; off = i - NX4 - NW4; }
        else                        { src = W2; dst = (__half2*)g_W2h; off = i - NX4 - 2 * NW4; }
        float4 v = src[off];
        __half2 lo = __floats2half2_rn(v.x, v.y);
        __half2 hi = __floats2half2_rn(v.z, v.w);
        dst[off * 2]     = lo;
        dst[off * 2 + 1] = hi;
    }
}

// ---------------------------------------------------------------------------
// 1) Router (one warp per token) — fp32 inputs, unchanged.
// ---------------------------------------------------------------------------
__global__ __launch_bounds__(256) void router_kernel(const float* __restrict__ x,
                                                     const float* __restrict__ Wg) {
    const int warp = (blockIdx.x * blockDim.x + threadIdx.x) >> 5;
    const int lane = threadIdx.x & 31;
    if (warp >= TOK) return;

    const float* xr = x + (size_t)warp * DDIM;
    float acc[NEXP];
#pragma unroll
    for (int e = 0; e < NEXP; e++) acc[e] = 0.f;

    for (int d = lane; d < DDIM; d += 32) {
        const float xv = xr[d];
        const float4 w0 = *reinterpret_cast<const float4*>(Wg + (size_t)d * NEXP);
        const float4 w1 = *reinterpret_cast<const float4*>(Wg + (size_t)d * NEXP + 4);
        acc[0] += xv * w0.x; acc[1] += xv * w0.y; acc[2] += xv * w0.z; acc[3] += xv * w0.w;
        acc[4] += xv * w1.x; acc[5] += xv * w1.y; acc[6] += xv * w1.z; acc[7] += xv * w1.w;
    }
#pragma unroll
    for (int off = 16; off > 0; off >>= 1) {
#pragma unroll
        for (int e = 0; e < NEXP; e++)
            acc[e] += __shfl_xor_sync(0xFFFFFFFFu, acc[e], off);
    }

    if (lane == 0) {
        int i0 = 0; float v0 = acc[0];
#pragma unroll
        for (int e = 1; e < NEXP; e++) if (acc[e] > v0) { v0 = acc[e]; i0 = e; }
        int i1 = -1; float v1 = -INFINITY;
#pragma unroll
        for (int e = 0; e < NEXP; e++)
            if (e != i0 && acc[e] > v1) { v1 = acc[e]; i1 = e; }

        const float e1 = expf(v1 - v0);
        const float inv = 1.f / (1.f + e1);
        g_gate[warp * 2 + 0] = inv;
        g_gate[warp * 2 + 1] = e1 * inv;

        int p0 = atomicAdd(&g_count[i0], 1);
        g_rows[i0 * TOK + p0] = warp;
        g_slot[i0 * TOK + p0] = warp * 2;
        int p1 = atomicAdd(&g_count[i1], 1);
        g_rows[i1 * TOK + p1] = warp;
        g_slot[i1 * TOK + p1] = warp * 2 + 1;
    }
}

// ---------------------------------------------------------------------------
// 2) Grouped dual GEMM + SwiGLU, fp16 HMMA. Block 256x64, 8 warps (4m x 2n),
//    warp 64x32 dual. cp.async 4-stage, ldmatrix fragments.
// Stage (bytes): A[256 rows x 32k fp16] @0 (16384), B1[32k x 64n] @16384 (4096),
// B3 @20480 (4096). Stage = 24576.
// ---------------------------------------------------------------------------
#define G1_SMEM_BYTES (1024 + 4 * 24576)
__global__ __launch_bounds__(256, 1) void gemm1_kernel() {
    extern __shared__ uint32_t dsm[];
    int* stok = reinterpret_cast<int*>(dsm);
    const uint32_t sb = smem_u32(dsm) + 1024;

    const int e   = blockIdx.y >> 5;
    const int mt  = blockIdx.y & 31;
    const int cnt = g_count[e];
    const int m0  = mt * 256;
    if (m0 >= cnt) return;
    const int n0 = blockIdx.x * 64;

    const int tid  = threadIdx.x;
    const int warp = tid >> 5;
    const int lane = tid & 31;
    const int wm = warp >> 1;
    const int wn = warp & 1;
    const int g  = lane >> 2;
    const int t  = lane & 3;

    {
        const int m = m0 + tid;
        stok[tid] = (m < cnt) ? g_rows[e * TOK + m] : g_rows[e * TOK];
    }
    __syncthreads();
    int tokp[4];
#pragma unroll
    for (int p = 0; p < 4; p++) tokp[p] = stok[p * 64 + (tid >> 2)];

    const __half* W1e = g_W1h + (size_t)e * DDIM * FDIM + n0;
    const __half* W3e = g_W3h + (size_t)e * DDIM * FDIM + n0;

    float acc1[4][4][4], acc3[4][4][4];
#pragma unroll
    for (int i = 0; i < 4; i++)
#pragma unroll
        for (int j = 0; j < 4; j++)
#pragma unroll
            for (int r = 0; r < 4; r++) { acc1[i][j][r] = 0.f; acc3[i][j][r] = 0.f; }

    auto issue = [&](int s, int k0) {
        const uint32_t base = sb + s * 24576;
#pragma unroll
        for (int p = 0; p < 4; p++) {
            const int id = p * 256 + tid;
            const int r = id >> 2, c = id & 3;
            const int cs = c ^ ((r >> 1) & 3);
            CP16(base + (uint32_t)(r * 64 + cs * 16),
                 g_X + (size_t)tokp[p] * DDIM + k0 + c * 8);
        }
        {
            const int k = tid >> 3, c = tid & 7;
            const int cs = c ^ (k & 7);
            CP16(base + 16384u + (uint32_t)(k * 128 + cs * 16),
                 W1e + (size_t)(k0 + k) * FDIM + c * 8);
            CP16(base + 20480u + (uint32_t)(k * 128 + cs * 16),
                 W3e + (size_t)(k0 + k) * FDIM + c * 8);
        }
        CPCOMMIT();
    };

    issue(0, 0); issue(1, BK); issue(2, 2 * BK);

    const int NCH = DDIM / BK;  // 32
    for (int c = 0; c < NCH; c++) {
        CPWAIT2();
        __syncthreads();
        if (c + 3 < NCH) issue((c + 3) & 3, (c + 3) * BK); else CPCOMMIT();

        const uint32_t sA  = sb + (c & 3) * 24576;
        const uint32_t sB1 = sA + 16384u;
        const uint32_t sB3 = sA + 20480u;
#pragma unroll
        for (int s = 0; s < 2; s++) {
            uint32_t af[4][4];
#pragma unroll
            for (int i = 0; i < 4; i++) {
                const int row = wm * 64 + i * 16 + (lane & 15);
                const int cc = 2 * s + (lane >> 4);
                const int cs = cc ^ ((row >> 1) & 3);
                ldsm4(af[i], sA + (uint32_t)(row * 64 + cs * 16));
            }
            const int kk = s * 16 + (lane & 7) + (lane & 8);
            uint32_t bf1[2][4], bf3[2][4];
#pragma unroll
            for (int jj = 0; jj < 2; jj++) {
                const int ci = wn * 4 + jj * 2 + (lane >> 4);
                const int cs = ci ^ (kk & 7);
                ldsm4t(bf1[jj], sB1 + (uint32_t)(kk * 128 + cs * 16));
                ldsm4t(bf3[jj], sB3 + (uint32_t)(kk * 128 + cs * 16));
            }
#pragma unroll
            for (int j = 0; j < 4; j++) {
                const int jj = j >> 1, h = (j & 1) * 2;
#pragma unroll
                for (int i = 0; i < 4; i++) {
                    mmah(acc1[i][j], af[i], bf1[jj][h], bf1[jj][h + 1]);
                    mmah(acc3[i][j], af[i], bf3[jj][h], bf3[jj][h + 1]);
                }
            }
        }
    }

    __half* Hbase = g_Hh + (size_t)e * TOK * FDIM;
    const int lim = cnt - m0;
#pragma unroll
    for (int i = 0; i < 4; i++) {
        const int lrow0 = wm * 64 + i * 16 + g;
        const int lrow1 = lrow0 + 8;
#pragma unroll
        for (int j = 0; j < 4; j++) {
            const int col = n0 + wn * 32 + j * 8 + 2 * t;
            if (lrow0 < lim) {
                const float z0 = acc1[i][j][0], z1 = acc1[i][j][1];
                __half2 hv = __floats2half2_rn(
                    (z0 / (1.f + expf(-z0))) * acc3[i][j][0],
                    (z1 / (1.f + expf(-z1))) * acc3[i][j][1]);
                *reinterpret_cast<__half2*>(Hbase + (size_t)(m0 + lrow0) * FDIM + col) = hv;
            }
            if (lrow1 < lim) {
                const float z2 = acc1[i][j][2], z3 = acc1[i][j][3];
                __half2 hv = __floats2half2_rn(
                    (z2 / (1.f + expf(-z2))) * acc3[i][j][2],
                    (z3 / (1.f + expf(-z3))) * acc3[i][j][3]);
                *reinterpret_cast<__half2*>(Hbase + (size_t)(m0 + lrow1) * FDIM + col) = hv;
            }
        }
    }
}

// ---------------------------------------------------------------------------
// 3) Grouped GEMM2, fp16 HMMA. Block 256x128, 8 warps (4m x 2n), warp 64x64.
// Stage: A[256x32k fp16] @0 (16384), B[32k x 128n fp16] @16384 (8192) = 24576.
// ---------------------------------------------------------------------------
#define G2_SMEM_BYTES (4 * 24576)
__global__ __launch_bounds__(256, 1) void gemm2_kernel() {
    extern __shared__ uint32_t dsm[];
    const uint32_t sb = smem_u32(dsm);

    const int e   = blockIdx.y >> 5;
    const int mt  = blockIdx.y & 31;
    const int cnt = g_count[e];
    const int m0  = mt * 256;
    if (m0 >= cnt) return;
    const int n0 = blockIdx.x * 128;

    const int tid  = threadIdx.x;
    const int warp = tid >> 5;
    const int lane = tid & 31;
    const int wm = warp >> 1;
    const int wn = warp & 1;
    const int g  = lane >> 2;
    const int t  = lane & 3;

    const __half* Hbase = g_Hh + ((size_t)e * TOK + m0) * FDIM;
    const __half* W2e   = g_W2h + (size_t)e * FDIM * DDIM + n0;

    float acc[4][8][4];
#pragma unroll
    for (int i = 0; i < 4; i++)
#pragma unroll
        for (int j = 0; j < 8; j++)
#pragma unroll
            for (int r = 0; r < 4; r++) acc[i][j][r] = 0.f;

    auto issue = [&](int s, int k0) {
        const uint32_t base = sb + s * 24576;
#pragma unroll
        for (int p = 0; p < 4; p++) {
            const int id = p * 256 + tid;
            const int r = id >> 2, c = id & 3;
            const int cs = c ^ ((r >> 1) & 3);
            CP16(base + (uint32_t)(r * 64 + cs * 16),
                 Hbase + (size_t)r * FDIM + k0 + c * 8);
        }
#pragma unroll
        for (int p = 0; p < 2; p++) {
            const int id = p * 256 + tid;
            const int k = id >> 4, c = id & 15;
            const int cs = c ^ (k & 7);
            CP16(base + 16384u + (uint32_t)(k * 256 + cs * 16),
                 W2e + (size_t)(k0 + k) * DDIM + c * 8);
        }
        CPCOMMIT();
    };

    issue(0, 0); issue(1, BK); issue(2, 2 * BK);

    const int NCH = FDIM / BK;  // 64
    for (int c = 0; c < NCH; c++) {
        CPWAIT2();
        __syncthreads();
        if (c + 3 < NCH) issue((c + 3) & 3, (c + 3) * BK); else CPCOMMIT();

        const uint32_t sA = sb + (c & 3) * 24576;
        const uint32_t sB = sA + 16384u;
#pragma unroll
        for (int s = 0; s < 2; s++) {
            uint32_t af[4][4];
#pragma unroll
            for (int i = 0; i < 4; i++) {
                const int row = wm * 64 + i * 16 + (lane & 15);
                const int cc = 2 * s + (lane >> 4);
                const int cs = cc ^ ((row >> 1) & 3);
                ldsm4(af[i], sA + (uint32_t)(row * 64 + cs * 16));
            }
            const int kk = s * 16 + (lane & 7) + (lane & 8);
            uint32_t bf[4][4];
#pragma unroll
            for (int jj = 0; jj < 4; jj++) {
                const int ci = wn * 8 + jj * 2 + (lane >> 4);
                const int cs = ci ^ (kk & 7);
                ldsm4t(bf[jj], sB + (uint32_t)(kk * 256 + cs * 16));
            }
#pragma unroll
            for (int j = 0; j < 8; j++) {
                const int jj = j >> 1, h = (j & 1) * 2;
#pragma unroll
                for (int i = 0; i < 4; i++)
                    mmah(acc[i][j], af[i], bf[jj][h], bf[jj][h + 1]);
            }
        }
    }

    const int lim = cnt - m0;
#pragma unroll
    for (int i = 0; i < 4; i++) {
        const int lrow0 = wm * 64 + i * 16 + g;
        const int lrow1 = lrow0 + 8;
        const int slot0 = (lrow0 < lim) ? g_slot[e * TOK + m0 + lrow0] : -1;
        const int slot1 = (lrow1 < lim) ? g_slot[e * TOK + m0 + lrow1] : -1;
#pragma unroll
        for (int j = 0; j < 8; j++) {
            const int col = n0 + wn * 64 + j * 8 + 2 * t;
            if (slot0 >= 0)
                *reinterpret_cast<float2*>(g_Y + (size_t)slot0 * DDIM + col) =
                    make_float2(acc[i][j][0], acc[i][j][1]);
            if (slot1 >= 0)
                *reinterpret_cast<float2*>(g_Y + (size_t)slot1 * DDIM + col) =
                    make_float2(acc[i][j][2], acc[i][j][3]);
        }
    }
}

// ---------------------------------------------------------------------------
// 4) Combine
// ---------------------------------------------------------------------------
__global__ __launch_bounds__(256) void combine_kernel(float* __restrict__ out) {
    const int tk = blockIdx.x;
    const int d = threadIdx.x * 4;
    const float g0 = g_gate[tk * 2 + 0];
    const float g1 = g_gate[tk * 2 + 1];
    const float4 y0 = *reinterpret_cast<const float4*>(g_Y + ((size_t)tk * 2 + 0) * DDIM + d);
    const float4 y1 = *reinterpret_cast<const float4*>(g_Y + ((size_t)tk * 2 + 1) * DDIM + d);
    float4 o;
    o.x = g0 * y0.x + g1 * y1.x;
    o.y = g0 * y0.y + g1 * y1.y;
    o.z = g0 * y0.z + g1 * y1.z;
    o.w = g0 * y0.w + g1 * y1.w;
    *reinterpret_cast<float4*>(out + (size_t)tk * DDIM + d) = o;
}

// ---------------------------------------------------------------------------
// Entry
// ---------------------------------------------------------------------------
extern "C" void kernel_launch(void* const* d_in, const int* in_sizes, int n_in,
                              void* d_out, int out_size) {
    const float* x  = (const float*)d_in[0];
    const float* Wg = (const float*)d_in[1];
    const float* W1 = (const float*)d_in[2];
    const float* W3 = (const float*)d_in[3];
    const float* W2 = (const float*)d_in[4];
    float* out = (float*)d_out;

    static int attr_done = 0;
    if (!attr_done) {
        cudaFuncSetAttribute(gemm1_kernel,
                             cudaFuncAttributeMaxDynamicSharedMemorySize, G1_SMEM_BYTES);
        cudaFuncSetAttribute(gemm2_kernel,
                             cudaFuncAttributeMaxDynamicSharedMemorySize, G2_SMEM_BYTES);
        attr_done = 1;
    }

    zero_counts_kernel<<<1, 32>>>();
    prep_kernel<<<4096, 256>>>((const float4*)x, (const float4*)W1,
                               (const float4*)W3, (const float4*)W2);
    router_kernel<<<TOK / 8, 256>>>(x, Wg);
    gemm1_kernel<<<dim3(FDIM / 64, NEXP * (TOK / 256)), 256, G1_SMEM_BYTES>>>();
    gemm2_kernel<<<dim3(DDIM / 128, NEXP * (TOK / 256)), 256, G2_SMEM_BYTES>>>();
    combine_kernel<<<TOK, 256>>>(out);
}

// round 13
// speedup vs baseline: 4.0121x; 1.0156x over previous
#include <cuda_runtime.h>
#include <cuda_fp16.h>
#include <math.h>
#include <stdint.h>

// Problem constants
#define TOK   8192
#define DDIM  1024
#define FDIM  2048
#define NEXP  8
#define TOPK  2

#define BK    32
#define NW4   ((size_t)NEXP * DDIM * FDIM / 4)
#define NX4   ((size_t)TOK * DDIM / 4)

// ---------------------------------------------------------------------------
// Scratch
// ---------------------------------------------------------------------------
__device__ int   g_count[NEXP];
__device__ int   g_rows [NEXP * TOK];
__device__ int   g_slot [NEXP * TOK];
__device__ float g_gate [TOK * TOPK];
__device__ __align__(16) float  g_Y  [(size_t)TOK * TOPK * DDIM];
// fp16 copies / intermediates
__device__ __align__(16) __half g_X  [(size_t)TOK * DDIM];
__device__ __align__(16) __half g_W1h[(size_t)NEXP * DDIM * FDIM];
__device__ __align__(16) __half g_W3h[(size_t)NEXP * DDIM * FDIM];
__device__ __align__(16) __half g_W2h[(size_t)NEXP * FDIM * DDIM];
__device__ __align__(16) __half g_Hh [(size_t)NEXP * TOK * FDIM];

// ---------------------------------------------------------------------------
// helpers
// ---------------------------------------------------------------------------
__device__ __forceinline__ uint32_t smem_u32(const void* p) {
    uint32_t a;
    asm("{ .reg .u64 t; cvta.to.shared.u64 t, %1; cvt.u32.u64 %0, t; }"
        : "=r"(a) : "l"(p));
    return a;
}

__device__ __forceinline__ void mmah(float c[4], const uint32_t a[4],
                                     uint32_t b0, uint32_t b1) {
    asm volatile(
        "mma.sync.aligned.m16n8k16.row.col.f32.f16.f16.f32 "
        "{%0,%1,%2,%3}, {%4,%5,%6,%7}, {%8,%9}, {%0,%1,%2,%3};"
        : "+f"(c[0]), "+f"(c[1]), "+f"(c[2]), "+f"(c[3])
        : "r"(a[0]), "r"(a[1]), "r"(a[2]), "r"(a[3]), "r"(b0), "r"(b1));
}

__device__ __forceinline__ void ldsm4(uint32_t r[4], uint32_t addr) {
    asm volatile("ldmatrix.sync.aligned.m8n8.x4.shared.b16 {%0,%1,%2,%3}, [%4];"
                 : "=r"(r[0]), "=r"(r[1]), "=r"(r[2]), "=r"(r[3]) : "r"(addr));
}

__device__ __forceinline__ void ldsm4t(uint32_t r[4], uint32_t addr) {
    asm volatile("ldmatrix.sync.aligned.m8n8.x4.trans.shared.b16 {%0,%1,%2,%3}, [%4];"
                 : "=r"(r[0]), "=r"(r[1]), "=r"(r[2]), "=r"(r[3]) : "r"(addr));
}

#define CP16(dst, src) \
    asm volatile("cp.async.cg.shared.global [%0], [%1], 16;" \
                 :: "r"(dst), "l"(src) : "memory")
#define CPCOMMIT() asm volatile("cp.async.commit_group;" ::: "memory")
#define CPWAIT2()  asm volatile("cp.async.wait_group 2;" ::: "memory")

// ---------------------------------------------------------------------------
// 0) zero expert counters
// ---------------------------------------------------------------------------
__global__ void zero_counts_kernel() {
    if (threadIdx.x < NEXP) g_count[threadIdx.x] = 0;
}

// ---------------------------------------------------------------------------
// 0b) Convert x, W1, W3, W2 to fp16 copies.
// ---------------------------------------------------------------------------
__global__ __launch_bounds__(256) void prep_kernel(const float4* __restrict__ x,
                                                   const float4* __restrict__ W1,
                                                   const float4* __restrict__ W3,
                                                   const float4* __restrict__ W2) {
    const size_t total = NX4 + 3 * NW4;
    const size_t stride = (size_t)gridDim.x * 256;
    for (size_t i = (size_t)blockIdx.x * 256 + threadIdx.x; i < total; i += stride) {
        const float4* src; __half2* dst; size_t off;
        if (i < NX4)                { src = x;  dst = (__half2*)g_X;   off = i; }
        else if (i < NX4 + NW4)     { src = W1; dst = (__half2*)g_W1h; off = i - NX4; }
        else if (i < NX4 + 2 * NW4) { src = W3; dst = (__half2*)g_W3h; off = i - NX4 - NW4; }
        else                        { src = W2; dst = (__half2*)g_W2h; off = i - NX4 - 2 * NW4; }
        float4 v = src[off];
        __half2 lo = __floats2half2_rn(v.x, v.y);
        __half2 hi = __floats2half2_rn(v.z, v.w);
        dst[off * 2]     = lo;
        dst[off * 2 + 1] = hi;
    }
}

// ---------------------------------------------------------------------------
// 1) Router (one warp per token)
// ---------------------------------------------------------------------------
__global__ __launch_bounds__(256) void router_kernel(const float* __restrict__ x,
                                                     const float* __restrict__ Wg) {
    const int warp = (blockIdx.x * blockDim.x + threadIdx.x) >> 5;
    const int lane = threadIdx.x & 31;
    if (warp >= TOK) return;

    const float* xr = x + (size_t)warp * DDIM;
    float acc[NEXP];
#pragma unroll
    for (int e = 0; e < NEXP; e++) acc[e] = 0.f;

    for (int d = lane; d < DDIM; d += 32) {
        const float xv = xr[d];
        const float4 w0 = *reinterpret_cast<const float4*>(Wg + (size_t)d * NEXP);
        const float4 w1 = *reinterpret_cast<const float4*>(Wg + (size_t)d * NEXP + 4);
        acc[0] += xv * w0.x; acc[1] += xv * w0.y; acc[2] += xv * w0.z; acc[3] += xv * w0.w;
        acc[4] += xv * w1.x; acc[5] += xv * w1.y; acc[6] += xv * w1.z; acc[7] += xv * w1.w;
    }
#pragma unroll
    for (int off = 16; off > 0; off >>= 1) {
#pragma unroll
        for (int e = 0; e < NEXP; e++)
            acc[e] += __shfl_xor_sync(0xFFFFFFFFu, acc[e], off);
    }

    if (lane == 0) {
        int i0 = 0; float v0 = acc[0];
#pragma unroll
        for (int e = 1; e < NEXP; e++) if (acc[e] > v0) { v0 = acc[e]; i0 = e; }
        int i1 = -1; float v1 = -INFINITY;
#pragma unroll
        for (int e = 0; e < NEXP; e++)
            if (e != i0 && acc[e] > v1) { v1 = acc[e]; i1 = e; }

        const float e1 = expf(v1 - v0);
        const float inv = 1.f / (1.f + e1);
        g_gate[warp * 2 + 0] = inv;
        g_gate[warp * 2 + 1] = e1 * inv;

        int p0 = atomicAdd(&g_count[i0], 1);
        g_rows[i0 * TOK + p0] = warp;
        g_slot[i0 * TOK + p0] = warp * 2;
        int p1 = atomicAdd(&g_count[i1], 1);
        g_rows[i1 * TOK + p1] = warp;
        g_slot[i1 * TOK + p1] = warp * 2 + 1;
    }
}

// ---------------------------------------------------------------------------
// 2) Grouped dual GEMM + SwiGLU, fp16 HMMA. Block 256x64, 512 threads,
//    16 warps (8m x 2n), warp 32x32 dual. cp.async 4-stage, ldmatrix.
// Stage (bytes): A[256 x 32k] @0 (16384), B1 @16384 (4096), B3 @20480 (4096).
// ---------------------------------------------------------------------------
#define G1_SMEM_BYTES (1024 + 4 * 24576)
__global__ __launch_bounds__(512, 1) void gemm1_kernel() {
    extern __shared__ uint32_t dsm[];
    int* stok = reinterpret_cast<int*>(dsm);
    const uint32_t sb = smem_u32(dsm) + 1024;

    const int e   = blockIdx.y >> 5;
    const int mt  = blockIdx.y & 31;
    const int cnt = g_count[e];
    const int m0  = mt * 256;
    if (m0 >= cnt) return;
    const int n0 = blockIdx.x * 64;

    const int tid  = threadIdx.x;
    const int warp = tid >> 5;
    const int lane = tid & 31;
    const int wm = warp >> 1;      // 0..7
    const int wn = warp & 1;       // 0..1
    const int g  = lane >> 2;
    const int t  = lane & 3;

    if (tid < 256) {
        const int m = m0 + tid;
        stok[tid] = (m < cnt) ? g_rows[e * TOK + m] : g_rows[e * TOK];
    }
    __syncthreads();
    int tokp[2];
#pragma unroll
    for (int p = 0; p < 2; p++) tokp[p] = stok[p * 128 + (tid >> 2)];

    const __half* W1e = g_W1h + (size_t)e * DDIM * FDIM + n0;
    const __half* W3e = g_W3h + (size_t)e * DDIM * FDIM + n0;

    float acc1[2][4][4], acc3[2][4][4];
#pragma unroll
    for (int i = 0; i < 2; i++)
#pragma unroll
        for (int j = 0; j < 4; j++)
#pragma unroll
            for (int r = 0; r < 4; r++) { acc1[i][j][r] = 0.f; acc3[i][j][r] = 0.f; }

    auto issue = [&](int s, int k0) {
        const uint32_t base = sb + s * 24576;
#pragma unroll
        for (int p = 0; p < 2; p++) {
            const int r = p * 128 + (tid >> 2);
            const int c = tid & 3;
            const int cs = c ^ ((r >> 1) & 3);
            CP16(base + (uint32_t)(r * 64 + cs * 16),
                 g_X + (size_t)tokp[p] * DDIM + k0 + c * 8);
        }
        {
            const int t2 = tid & 255;
            const int k = t2 >> 3, c = t2 & 7;
            const int cs = c ^ (k & 7);
            if (tid < 256)
                CP16(base + 16384u + (uint32_t)(k * 128 + cs * 16),
                     W1e + (size_t)(k0 + k) * FDIM + c * 8);
            else
                CP16(base + 20480u + (uint32_t)(k * 128 + cs * 16),
                     W3e + (size_t)(k0 + k) * FDIM + c * 8);
        }
        CPCOMMIT();
    };

    issue(0, 0); issue(1, BK); issue(2, 2 * BK);

    const int NCH = DDIM / BK;  // 32
    for (int c = 0; c < NCH; c++) {
        CPWAIT2();
        __syncthreads();
        if (c + 3 < NCH) issue((c + 3) & 3, (c + 3) * BK); else CPCOMMIT();

        const uint32_t sA  = sb + (c & 3) * 24576;
        const uint32_t sB1 = sA + 16384u;
        const uint32_t sB3 = sA + 20480u;
#pragma unroll
        for (int s = 0; s < 2; s++) {
            uint32_t af[2][4];
#pragma unroll
            for (int i = 0; i < 2; i++) {
                const int row = wm * 32 + i * 16 + (lane & 15);
                const int cc = 2 * s + (lane >> 4);
                const int cs = cc ^ ((row >> 1) & 3);
                ldsm4(af[i], sA + (uint32_t)(row * 64 + cs * 16));
            }
            const int kk = s * 16 + (lane & 7) + (lane & 8);
            uint32_t bf1[2][4], bf3[2][4];
#pragma unroll
            for (int jj = 0; jj < 2; jj++) {
                const int ci = wn * 4 + jj * 2 + (lane >> 4);
                const int cs = ci ^ (kk & 7);
                ldsm4t(bf1[jj], sB1 + (uint32_t)(kk * 128 + cs * 16));
                ldsm4t(bf3[jj], sB3 + (uint32_t)(kk * 128 + cs * 16));
            }
#pragma unroll
            for (int j = 0; j < 4; j++) {
                const int jj = j >> 1, h = (j & 1) * 2;
#pragma unroll
                for (int i = 0; i < 2; i++) {
                    mmah(acc1[i][j], af[i], bf1[jj][h], bf1[jj][h + 1]);
                    mmah(acc3[i][j], af[i], bf3[jj][h], bf3[jj][h + 1]);
                }
            }
        }
    }

    __half* Hbase = g_Hh + (size_t)e * TOK * FDIM;
    const int lim = cnt - m0;
#pragma unroll
    for (int i = 0; i < 2; i++) {
        const int lrow0 = wm * 32 + i * 16 + g;
        const int lrow1 = lrow0 + 8;
#pragma unroll
        for (int j = 0; j < 4; j++) {
            const int col = n0 + wn * 32 + j * 8 + 2 * t;
            if (lrow0 < lim) {
                const float z0 = acc1[i][j][0], z1 = acc1[i][j][1];
                __half2 hv = __floats2half2_rn(
                    (z0 / (1.f + expf(-z0))) * acc3[i][j][0],
                    (z1 / (1.f + expf(-z1))) * acc3[i][j][1]);
                *reinterpret_cast<__half2*>(Hbase + (size_t)(m0 + lrow0) * FDIM + col) = hv;
            }
            if (lrow1 < lim) {
                const float z2 = acc1[i][j][2], z3 = acc1[i][j][3];
                __half2 hv = __floats2half2_rn(
                    (z2 / (1.f + expf(-z2))) * acc3[i][j][2],
                    (z3 / (1.f + expf(-z3))) * acc3[i][j][3]);
                *reinterpret_cast<__half2*>(Hbase + (size_t)(m0 + lrow1) * FDIM + col) = hv;
            }
        }
    }
}

// ---------------------------------------------------------------------------
// 3) Grouped GEMM2, fp16 HMMA. Block 256x128, 512 threads, 16 warps (4m x 4n),
//    warp 64x32. Stage: A @0 (16384), B @16384 (8192) = 24576.
// ---------------------------------------------------------------------------
#define G2_SMEM_BYTES (4 * 24576)
__global__ __launch_bounds__(512, 1) void gemm2_kernel() {
    extern __shared__ uint32_t dsm[];
    const uint32_t sb = smem_u32(dsm);

    const int e   = blockIdx.y >> 5;
    const int mt  = blockIdx.y & 31;
    const int cnt = g_count[e];
    const int m0  = mt * 256;
    if (m0 >= cnt) return;
    const int n0 = blockIdx.x * 128;

    const int tid  = threadIdx.x;
    const int warp = tid >> 5;
    const int lane = tid & 31;
    const int wm = warp >> 2;      // 0..3
    const int wn = warp & 3;       // 0..3
    const int g  = lane >> 2;
    const int t  = lane & 3;

    const __half* Hbase = g_Hh + ((size_t)e * TOK + m0) * FDIM;
    const __half* W2e   = g_W2h + (size_t)e * FDIM * DDIM + n0;

    float acc[4][4][4];
#pragma unroll
    for (int i = 0; i < 4; i++)
#pragma unroll
        for (int j = 0; j < 4; j++)
#pragma unroll
            for (int r = 0; r < 4; r++) acc[i][j][r] = 0.f;

    auto issue = [&](int s, int k0) {
        const uint32_t base = sb + s * 24576;
#pragma unroll
        for (int p = 0; p < 2; p++) {
            const int r = p * 128 + (tid >> 2);
            const int c = tid & 3;
            const int cs = c ^ ((r >> 1) & 3);
            CP16(base + (uint32_t)(r * 64 + cs * 16),
                 Hbase + (size_t)r * FDIM + k0 + c * 8);
        }
        {
            const int k = tid >> 4, c = tid & 15;
            const int cs = c ^ (k & 7);
            CP16(base + 16384u + (uint32_t)(k * 256 + cs * 16),
                 W2e + (size_t)(k0 + k) * DDIM + c * 8);
        }
        CPCOMMIT();
    };

    issue(0, 0); issue(1, BK); issue(2, 2 * BK);

    const int NCH = FDIM / BK;  // 64
    for (int c = 0; c < NCH; c++) {
        CPWAIT2();
        __syncthreads();
        if (c + 3 < NCH) issue((c + 3) & 3, (c + 3) * BK); else CPCOMMIT();

        const uint32_t sA = sb + (c & 3) * 24576;
        const uint32_t sB = sA + 16384u;
#pragma unroll
        for (int s = 0; s < 2; s++) {
            uint32_t af[4][4];
#pragma unroll
            for (int i = 0; i < 4; i++) {
                const int row = wm * 64 + i * 16 + (lane & 15);
                const int cc = 2 * s + (lane >> 4);
                const int cs = cc ^ ((row >> 1) & 3);
                ldsm4(af[i], sA + (uint32_t)(row * 64 + cs * 16));
            }
            const int kk = s * 16 + (lane & 7) + (lane & 8);
            uint32_t bf[2][4];
#pragma unroll
            for (int jj = 0; jj < 2; jj++) {
                const int ci = wn * 4 + jj * 2 + (lane >> 4);
                const int cs = ci ^ (kk & 7);
                ldsm4t(bf[jj], sB + (uint32_t)(kk * 256 + cs * 16));
            }
#pragma unroll
            for (int j = 0; j < 4; j++) {
                const int jj = j >> 1, h = (j & 1) * 2;
#pragma unroll
                for (int i = 0; i < 4; i++)
                    mmah(acc[i][j], af[i], bf[jj][h], bf[jj][h + 1]);
            }
        }
    }

    const int lim = cnt - m0;
#pragma unroll
    for (int i = 0; i < 4; i++) {
        const int lrow0 = wm * 64 + i * 16 + g;
        const int lrow1 = lrow0 + 8;
        const int slot0 = (lrow0 < lim) ? g_slot[e * TOK + m0 + lrow0] : -1;
        const int slot1 = (lrow1 < lim) ? g_slot[e * TOK + m0 + lrow1] : -1;
#pragma unroll
        for (int j = 0; j < 4; j++) {
            const int col = n0 + wn * 32 + j * 8 + 2 * t;
            if (slot0 >= 0)
                *reinterpret_cast<float2*>(g_Y + (size_t)slot0 * DDIM + col) =
                    make_float2(acc[i][j][0], acc[i][j][1]);
            if (slot1 >= 0)
                *reinterpret_cast<float2*>(g_Y + (size_t)slot1 * DDIM + col) =
                    make_float2(acc[i][j][2], acc[i][j][3]);
        }
    }
}

// ---------------------------------------------------------------------------
// 4) Combine
// ---------------------------------------------------------------------------
__global__ __launch_bounds__(256) void combine_kernel(float* __restrict__ out) {
    const int tk = blockIdx.x;
    const int d = threadIdx.x * 4;
    const float g0 = g_gate[tk * 2 + 0];
    const float g1 = g_gate[tk * 2 + 1];
    const float4 y0 = *reinterpret_cast<const float4*>(g_Y + ((size_t)tk * 2 + 0) * DDIM + d);
    const float4 y1 = *reinterpret_cast<const float4*>(g_Y + ((size_t)tk * 2 + 1) * DDIM + d);
    float4 o;
    o.x = g0 * y0.x + g1 * y1.x;
    o.y = g0 * y0.y + g1 * y1.y;
    o.z = g0 * y0.z + g1 * y1.z;
    o.w = g0 * y0.w + g1 * y1.w;
    *reinterpret_cast<float4*>(out + (size_t)tk * DDIM + d) = o;
}

// ---------------------------------------------------------------------------
// Entry
// ---------------------------------------------------------------------------
extern "C" void kernel_launch(void* const* d_in, const int* in_sizes, int n_in,
                              void* d_out, int out_size) {
    const float* x  = (const float*)d_in[0];
    const float* Wg = (const float*)d_in[1];
    const float* W1 = (const float*)d_in[2];
    const float* W3 = (const float*)d_in[3];
    const float* W2 = (const float*)d_in[4];
    float* out = (float*)d_out;

    static int attr_done = 0;
    if (!attr_done) {
        cudaFuncSetAttribute(gemm1_kernel,
                             cudaFuncAttributeMaxDynamicSharedMemorySize, G1_SMEM_BYTES);
        cudaFuncSetAttribute(gemm2_kernel,
                             cudaFuncAttributeMaxDynamicSharedMemorySize, G2_SMEM_BYTES);
        attr_done = 1;
    }

    zero_counts_kernel<<<1, 32>>>();
    prep_kernel<<<4096, 256>>>((const float4*)x, (const float4*)W1,
                               (const float4*)W3, (const float4*)W2);
    router_kernel<<<TOK / 8, 256>>>(x, Wg);
    gemm1_kernel<<<dim3(FDIM / 64, NEXP * (TOK / 256)), 512, G1_SMEM_BYTES>>>();
    gemm2_kernel<<<dim3(DDIM / 128, NEXP * (TOK / 256)), 512, G2_SMEM_BYTES>>>();
    combine_kernel<<<TOK, 256>>>(out);
}

// round 14
// speedup vs baseline: 4.5327x; 1.1298x over previous
#include <cuda_runtime.h>
#include <cuda_fp16.h>
#include <math.h>
#include <stdint.h>

// Problem constants
#define TOK   8192
#define DDIM  1024
#define FDIM  2048
#define NEXP  8
#define TOPK  2

#define BK    64
#define NW4   ((size_t)NEXP * DDIM * FDIM / 4)

// ---------------------------------------------------------------------------
// Scratch
// ---------------------------------------------------------------------------
__device__ int   g_count[NEXP];
__device__ int   g_rows [NEXP * TOK];
__device__ int   g_slot [NEXP * TOK];
__device__ float g_gate [TOK * TOPK];
__device__ __align__(16) float  g_Y  [(size_t)TOK * TOPK * DDIM];
__device__ __align__(16) __half g_X  [(size_t)TOK * DDIM];
__device__ __align__(16) __half g_W1h[(size_t)NEXP * DDIM * FDIM];
__device__ __align__(16) __half g_W3h[(size_t)NEXP * DDIM * FDIM];
__device__ __align__(16) __half g_W2h[(size_t)NEXP * FDIM * DDIM];
__device__ __align__(16) __half g_Hh [(size_t)NEXP * TOK * FDIM];

// ---------------------------------------------------------------------------
// helpers
// ---------------------------------------------------------------------------
__device__ __forceinline__ uint32_t smem_u32(const void* p) {
    uint32_t a;
    asm("{ .reg .u64 t; cvta.to.shared.u64 t, %1; cvt.u32.u64 %0, t; }"
        : "=r"(a) : "l"(p));
    return a;
}

__device__ __forceinline__ void mmah(float c[4], const uint32_t a[4],
                                     uint32_t b0, uint32_t b1) {
    asm volatile(
        "mma.sync.aligned.m16n8k16.row.col.f32.f16.f16.f32 "
        "{%0,%1,%2,%3}, {%4,%5,%6,%7}, {%8,%9}, {%0,%1,%2,%3};"
        : "+f"(c[0]), "+f"(c[1]), "+f"(c[2]), "+f"(c[3])
        : "r"(a[0]), "r"(a[1]), "r"(a[2]), "r"(a[3]), "r"(b0), "r"(b1));
}

__device__ __forceinline__ void ldsm4(uint32_t r[4], uint32_t addr) {
    asm volatile("ldmatrix.sync.aligned.m8n8.x4.shared.b16 {%0,%1,%2,%3}, [%4];"
                 : "=r"(r[0]), "=r"(r[1]), "=r"(r[2]), "=r"(r[3]) : "r"(addr));
}

__device__ __forceinline__ void ldsm4t(uint32_t r[4], uint32_t addr) {
    asm volatile("ldmatrix.sync.aligned.m8n8.x4.trans.shared.b16 {%0,%1,%2,%3}, [%4];"
                 : "=r"(r[0]), "=r"(r[1]), "=r"(r[2]), "=r"(r[3]) : "r"(addr));
}

#define CP16(dst, src) \
    asm volatile("cp.async.cg.shared.global [%0], [%1], 16;" \
                 :: "r"(dst), "l"(src) : "memory")
#define CPCOMMIT() asm volatile("cp.async.commit_group;" ::: "memory")
#define CPWAIT1()  asm volatile("cp.async.wait_group 1;" ::: "memory")

// ---------------------------------------------------------------------------
// 0) zero expert counters
// ---------------------------------------------------------------------------
__global__ void zero_counts_kernel() {
    if (threadIdx.x < NEXP) g_count[threadIdx.x] = 0;
}

// ---------------------------------------------------------------------------
// 0b) Convert W1, W3, W2 to fp16 copies (x handled in router).
// ---------------------------------------------------------------------------
__global__ __launch_bounds__(256) void prep_kernel(const float4* __restrict__ W1,
                                                   const float4* __restrict__ W3,
                                                   const float4* __restrict__ W2) {
    const size_t total = 3 * NW4;
    const size_t stride = (size_t)gridDim.x * 256;
    for (size_t i = (size_t)blockIdx.x * 256 + threadIdx.x; i < total; i += stride) {
        const float4* src; __half2* dst; size_t off;
        if (i < NW4)            { src = W1; dst = (__half2*)g_W1h; off = i; }
        else if (i < 2 * NW4)   { src = W3; dst = (__half2*)g_W3h; off = i - NW4; }
        else                    { src = W2; dst = (__half2*)g_W2h; off = i - 2 * NW4; }
        float4 v = src[off];
        dst[off * 2]     = __floats2half2_rn(v.x, v.y);
        dst[off * 2 + 1] = __floats2half2_rn(v.z, v.w);
    }
}

// ---------------------------------------------------------------------------
// 1) Router (one warp per token) — also emits fp16 copy of x.
// ---------------------------------------------------------------------------
__global__ __launch_bounds__(256) void router_kernel(const float* __restrict__ x,
                                                     const float* __restrict__ Wg) {
    const int warp = (blockIdx.x * blockDim.x + threadIdx.x) >> 5;
    const int lane = threadIdx.x & 31;
    if (warp >= TOK) return;

    const float* xr = x + (size_t)warp * DDIM;
    __half* xh = g_X + (size_t)warp * DDIM;
    float acc[NEXP];
#pragma unroll
    for (int e = 0; e < NEXP; e++) acc[e] = 0.f;

    for (int d = lane; d < DDIM; d += 32) {
        const float xv = xr[d];
        xh[d] = __float2half_rn(xv);
        const float4 w0 = *reinterpret_cast<const float4*>(Wg + (size_t)d * NEXP);
        const float4 w1 = *reinterpret_cast<const float4*>(Wg + (size_t)d * NEXP + 4);
        acc[0] += xv * w0.x; acc[1] += xv * w0.y; acc[2] += xv * w0.z; acc[3] += xv * w0.w;
        acc[4] += xv * w1.x; acc[5] += xv * w1.y; acc[6] += xv * w1.z; acc[7] += xv * w1.w;
    }
#pragma unroll
    for (int off = 16; off > 0; off >>= 1) {
#pragma unroll
        for (int e = 0; e < NEXP; e++)
            acc[e] += __shfl_xor_sync(0xFFFFFFFFu, acc[e], off);
    }

    if (lane == 0) {
        int i0 = 0; float v0 = acc[0];
#pragma unroll
        for (int e = 1; e < NEXP; e++) if (acc[e] > v0) { v0 = acc[e]; i0 = e; }
        int i1 = -1; float v1 = -INFINITY;
#pragma unroll
        for (int e = 0; e < NEXP; e++)
            if (e != i0 && acc[e] > v1) { v1 = acc[e]; i1 = e; }

        const float e1 = expf(v1 - v0);
        const float inv = 1.f / (1.f + e1);
        g_gate[warp * 2 + 0] = inv;
        g_gate[warp * 2 + 1] = e1 * inv;

        int p0 = atomicAdd(&g_count[i0], 1);
        g_rows[i0 * TOK + p0] = warp;
        g_slot[i0 * TOK + p0] = warp * 2;
        int p1 = atomicAdd(&g_count[i1], 1);
        g_rows[i1 * TOK + p1] = warp;
        g_slot[i1 * TOK + p1] = warp * 2 + 1;
    }
}

// ---------------------------------------------------------------------------
// 2) Grouped dual GEMM + SwiGLU, fp16 HMMA. Block 256x64, 512 threads,
//    16 warps (8m x 2n), warp 32x32 dual. BK=64, 3-stage cp.async.
// Stage (bytes): A[256 x 64k] @0 (32768, 128B rows, chunk^=(row&7)),
//                B1[64k x 64n] @32768 (8192), B3 @40960 (8192). Stage 49152.
// ---------------------------------------------------------------------------
#define G1_SMEM_BYTES (1024 + 3 * 49152)
__global__ __launch_bounds__(512, 1) void gemm1_kernel() {
    extern __shared__ uint32_t dsm[];
    int* stok = reinterpret_cast<int*>(dsm);
    const uint32_t sb = smem_u32(dsm) + 1024;

    const int e   = blockIdx.y >> 5;
    const int mt  = blockIdx.y & 31;
    const int cnt = g_count[e];
    const int m0  = mt * 256;
    if (m0 >= cnt) return;
    const int n0 = blockIdx.x * 64;

    const int tid  = threadIdx.x;
    const int warp = tid >> 5;
    const int lane = tid & 31;
    const int wm = warp >> 1;      // 0..7
    const int wn = warp & 1;       // 0..1
    const int g  = lane >> 2;
    const int t  = lane & 3;

    if (tid < 256) {
        const int m = m0 + tid;
        stok[tid] = (m < cnt) ? g_rows[e * TOK + m] : g_rows[e * TOK];
    }
    __syncthreads();
    int tokp[4];
#pragma unroll
    for (int p = 0; p < 4; p++) tokp[p] = stok[p * 64 + (tid >> 3)];

    const __half* W1e = g_W1h + (size_t)e * DDIM * FDIM + n0;
    const __half* W3e = g_W3h + (size_t)e * DDIM * FDIM + n0;

    float acc1[2][4][4], acc3[2][4][4];
#pragma unroll
    for (int i = 0; i < 2; i++)
#pragma unroll
        for (int j = 0; j < 4; j++)
#pragma unroll
            for (int r = 0; r < 4; r++) { acc1[i][j][r] = 0.f; acc3[i][j][r] = 0.f; }

    const int rA = tid >> 3;       // 0..63 (sub-row within pass)
    const int cA = tid & 7;        // chunk 0..7
    const int kB = tid >> 3;       // 0..63 k-row
    const int cB = tid & 7;        // chunk 0..7

    auto issue = [&](int s, int k0) {
        const uint32_t base = sb + s * 49152;
#pragma unroll
        for (int p = 0; p < 4; p++) {
            const int r = p * 64 + rA;
            const int cs = cA ^ (r & 7);
            CP16(base + (uint32_t)(r * 128 + cs * 16),
                 g_X + (size_t)tokp[p] * DDIM + k0 + cA * 8);
        }
        {
            const int cs = cB ^ (kB & 7);
            CP16(base + 32768u + (uint32_t)(kB * 128 + cs * 16),
                 W1e + (size_t)(k0 + kB) * FDIM + cB * 8);
            CP16(base + 40960u + (uint32_t)(kB * 128 + cs * 16),
                 W3e + (size_t)(k0 + kB) * FDIM + cB * 8);
        }
        CPCOMMIT();
    };

    issue(0, 0); issue(1, BK);

    const int NCH = DDIM / BK;  // 16
    for (int c = 0; c < NCH; c++) {
        CPWAIT1();
        __syncthreads();
        if (c + 2 < NCH) issue((c + 2) % 3, (c + 2) * BK); else CPCOMMIT();

        const uint32_t sA  = sb + (c % 3) * 49152;
        const uint32_t sB1 = sA + 32768u;
        const uint32_t sB3 = sA + 40960u;
#pragma unroll
        for (int s = 0; s < 4; s++) {
            uint32_t af[2][4];
#pragma unroll
            for (int i = 0; i < 2; i++) {
                const int row = wm * 32 + i * 16 + (lane & 15);
                const int cc = 2 * s + (lane >> 4);
                const int cs = cc ^ (row & 7);
                ldsm4(af[i], sA + (uint32_t)(row * 128 + cs * 16));
            }
            const int kk = s * 16 + (lane & 7) + (lane & 8);
            uint32_t bf1[2][4], bf3[2][4];
#pragma unroll
            for (int jj = 0; jj < 2; jj++) {
                const int ci = wn * 4 + jj * 2 + (lane >> 4);
                const int cs = ci ^ (kk & 7);
                ldsm4t(bf1[jj], sB1 + (uint32_t)(kk * 128 + cs * 16));
                ldsm4t(bf3[jj], sB3 + (uint32_t)(kk * 128 + cs * 16));
            }
#pragma unroll
            for (int j = 0; j < 4; j++) {
                const int jj = j >> 1, h = (j & 1) * 2;
#pragma unroll
                for (int i = 0; i < 2; i++) {
                    mmah(acc1[i][j], af[i], bf1[jj][h], bf1[jj][h + 1]);
                    mmah(acc3[i][j], af[i], bf3[jj][h], bf3[jj][h + 1]);
                }
            }
        }
    }

    __half* Hbase = g_Hh + (size_t)e * TOK * FDIM;
    const int lim = cnt - m0;
#pragma unroll
    for (int i = 0; i < 2; i++) {
        const int lrow0 = wm * 32 + i * 16 + g;
        const int lrow1 = lrow0 + 8;
#pragma unroll
        for (int j = 0; j < 4; j++) {
            const int col = n0 + wn * 32 + j * 8 + 2 * t;
            if (lrow0 < lim) {
                const float z0 = acc1[i][j][0], z1 = acc1[i][j][1];
                __half2 hv = __floats2half2_rn(
                    (z0 / (1.f + expf(-z0))) * acc3[i][j][0],
                    (z1 / (1.f + expf(-z1))) * acc3[i][j][1]);
                *reinterpret_cast<__half2*>(Hbase + (size_t)(m0 + lrow0) * FDIM + col) = hv;
            }
            if (lrow1 < lim) {
                const float z2 = acc1[i][j][2], z3 = acc1[i][j][3];
                __half2 hv = __floats2half2_rn(
                    (z2 / (1.f + expf(-z2))) * acc3[i][j][2],
                    (z3 / (1.f + expf(-z3))) * acc3[i][j][3]);
                *reinterpret_cast<__half2*>(Hbase + (size_t)(m0 + lrow1) * FDIM + col) = hv;
            }
        }
    }
}

// ---------------------------------------------------------------------------
// 3) Grouped GEMM2, fp16 HMMA. Block 256x128, 512 threads, 16 warps (4m x 4n),
//    warp 64x32. BK=64, 3-stage. Stage: A @0 (32768), B[64k x 128n] @32768
//    (16384, 256B rows / 16 chunks, chunk^=(k&7)). Stage 49152.
// ---------------------------------------------------------------------------
#define G2_SMEM_BYTES (3 * 49152)
__global__ __launch_bounds__(512, 1) void gemm2_kernel() {
    extern __shared__ uint32_t dsm[];
    const uint32_t sb = smem_u32(dsm);

    const int e   = blockIdx.y >> 5;
    const int mt  = blockIdx.y & 31;
    const int cnt = g_count[e];
    const int m0  = mt * 256;
    if (m0 >= cnt) return;
    const int n0 = blockIdx.x * 128;

    const int tid  = threadIdx.x;
    const int warp = tid >> 5;
    const int lane = tid & 31;
    const int wm = warp >> 2;      // 0..3
    const int wn = warp & 3;       // 0..3
    const int g  = lane >> 2;
    const int t  = lane & 3;

    const __half* Hbase = g_Hh + ((size_t)e * TOK + m0) * FDIM;
    const __half* W2e   = g_W2h + (size_t)e * FDIM * DDIM + n0;

    float acc[4][4][4];
#pragma unroll
    for (int i = 0; i < 4; i++)
#pragma unroll
        for (int j = 0; j < 4; j++)
#pragma unroll
            for (int r = 0; r < 4; r++) acc[i][j][r] = 0.f;

    const int rA = tid >> 3;
    const int cA = tid & 7;
    const int kB = tid >> 4;       // 0..31 (2 passes cover 64 k-rows)
    const int cB = tid & 15;       // chunk 0..15

    auto issue = [&](int s, int k0) {
        const uint32_t base = sb + s * 49152;
#pragma unroll
        for (int p = 0; p < 4; p++) {
            const int r = p * 64 + rA;
            const int cs = cA ^ (r & 7);
            CP16(base + (uint32_t)(r * 128 + cs * 16),
                 Hbase + (size_t)r * FDIM + k0 + cA * 8);
        }
#pragma unroll
        for (int p = 0; p < 2; p++) {
            const int k = p * 32 + kB;
            const int cs = cB ^ (k & 7);
            CP16(base + 32768u + (uint32_t)(k * 256 + cs * 16),
                 W2e + (size_t)(k0 + k) * DDIM + cB * 8);
        }
        CPCOMMIT();
    };

    issue(0, 0); issue(1, BK);

    const int NCH = FDIM / BK;  // 32
    for (int c = 0; c < NCH; c++) {
        CPWAIT1();
        __syncthreads();
        if (c + 2 < NCH) issue((c + 2) % 3, (c + 2) * BK); else CPCOMMIT();

        const uint32_t sA = sb + (c % 3) * 49152;
        const uint32_t sB = sA + 32768u;
#pragma unroll
        for (int s = 0; s < 4; s++) {
            uint32_t af[4][4];
#pragma unroll
            for (int i = 0; i < 4; i++) {
                const int row = wm * 64 + i * 16 + (lane & 15);
                const int cc = 2 * s + (lane >> 4);
                const int cs = cc ^ (row & 7);
                ldsm4(af[i], sA + (uint32_t)(row * 128 + cs * 16));
            }
            const int kk = s * 16 + (lane & 7) + (lane & 8);
            uint32_t bf[2][4];
#pragma unroll
            for (int jj = 0; jj < 2; jj++) {
                const int ci = wn * 4 + jj * 2 + (lane >> 4);
                const int cs = ci ^ (kk & 7);
                ldsm4t(bf[jj], sB + (uint32_t)(kk * 256 + cs * 16));
            }
#pragma unroll
            for (int j = 0; j < 4; j++) {
                const int jj = j >> 1, h = (j & 1) * 2;
#pragma unroll
                for (int i = 0; i < 4; i++)
                    mmah(acc[i][j], af[i], bf[jj][h], bf[jj][h + 1]);
            }
        }
    }

    const int lim = cnt - m0;
#pragma unroll
    for (int i = 0; i < 4; i++) {
        const int lrow0 = wm * 64 + i * 16 + g;
        const int lrow1 = lrow0 + 8;
        const int slot0 = (lrow0 < lim) ? g_slot[e * TOK + m0 + lrow0] : -1;
        const int slot1 = (lrow1 < lim) ? g_slot[e * TOK + m0 + lrow1] : -1;
#pragma unroll
        for (int j = 0; j < 4; j++) {
            const int col = n0 + wn * 32 + j * 8 + 2 * t;
            if (slot0 >= 0)
                *reinterpret_cast<float2*>(g_Y + (size_t)slot0 * DDIM + col) =
                    make_float2(acc[i][j][0], acc[i][j][1]);
            if (slot1 >= 0)
                *reinterpret_cast<float2*>(g_Y + (size_t)slot1 * DDIM + col) =
                    make_float2(acc[i][j][2], acc[i][j][3]);
        }
    }
}

// ---------------------------------------------------------------------------
// 4) Combine
// ---------------------------------------------------------------------------
__global__ __launch_bounds__(256) void combine_kernel(float* __restrict__ out) {
    const int tk = blockIdx.x;
    const int d = threadIdx.x * 4;
    const float g0 = g_gate[tk * 2 + 0];
    const float g1 = g_gate[tk * 2 + 1];
    const float4 y0 = *reinterpret_cast<const float4*>(g_Y + ((size_t)tk * 2 + 0) * DDIM + d);
    const float4 y1 = *reinterpret_cast<const float4*>(g_Y + ((size_t)tk * 2 + 1) * DDIM + d);
    float4 o;
    o.x = g0 * y0.x + g1 * y1.x;
    o.y = g0 * y0.y + g1 * y1.y;
    o.z = g0 * y0.z + g1 * y1.z;
    o.w = g0 * y0.w + g1 * y1.w;
    *reinterpret_cast<float4*>(out + (size_t)tk * DDIM + d) = o;
}

// ---------------------------------------------------------------------------
// Entry
// ---------------------------------------------------------------------------
extern "C" void kernel_launch(void* const* d_in, const int* in_sizes, int n_in,
                              void* d_out, int out_size) {
    const float* x  = (const float*)d_in[0];
    const float* Wg = (const float*)d_in[1];
    const float* W1 = (const float*)d_in[2];
    const float* W3 = (const float*)d_in[3];
    const float* W2 = (const float*)d_in[4];
    float* out = (float*)d_out;

    static int attr_done = 0;
    if (!attr_done) {
        cudaFuncSetAttribute(gemm1_kernel,
                             cudaFuncAttributeMaxDynamicSharedMemorySize, G1_SMEM_BYTES);
        cudaFuncSetAttribute(gemm2_kernel,
                             cudaFuncAttributeMaxDynamicSharedMemorySize, G2_SMEM_BYTES);
        attr_done = 1;
    }

    zero_counts_kernel<<<1, 32>>>();
    prep_kernel<<<4096, 256>>>((const float4*)W1, (const float4*)W3, (const float4*)W2);
    router_kernel<<<TOK / 8, 256>>>(x, Wg);
    gemm1_kernel<<<dim3(FDIM / 64, NEXP * (TOK / 256)), 512, G1_SMEM_BYTES>>>();
    gemm2_kernel<<<dim3(DDIM / 128, NEXP * (TOK / 256)), 512, G2_SMEM_BYTES>>>();
    combine_kernel<<<TOK, 256>>>(out);
}

// round 15
// speedup vs baseline: 4.6300x; 1.0215x over previous
#include <cuda_runtime.h>
#include <cuda_fp16.h>
#include <math.h>
#include <stdint.h>

// Problem constants
#define TOK   8192
#define DDIM  1024
#define FDIM  2048
#define NEXP  8
#define TOPK  2

#define BK    64
#define NW4   ((size_t)NEXP * DDIM * FDIM / 4)

// ---------------------------------------------------------------------------
// Scratch
// ---------------------------------------------------------------------------
__device__ int   g_count[NEXP];
__device__ int   g_rows [NEXP * TOK];
__device__ int   g_slot [NEXP * TOK];
__device__ float g_gate [TOK * TOPK];
__device__ __align__(16) float  g_Y  [(size_t)TOK * TOPK * DDIM];
__device__ __align__(16) __half g_X  [(size_t)TOK * DDIM];
__device__ __align__(16) __half g_W1h[(size_t)NEXP * DDIM * FDIM];
__device__ __align__(16) __half g_W3h[(size_t)NEXP * DDIM * FDIM];
__device__ __align__(16) __half g_W2h[(size_t)NEXP * FDIM * DDIM];
__device__ __align__(16) __half g_Hh [(size_t)NEXP * TOK * FDIM];

// ---------------------------------------------------------------------------
// helpers
// ---------------------------------------------------------------------------
__device__ __forceinline__ uint32_t smem_u32(const void* p) {
    uint32_t a;
    asm("{ .reg .u64 t; cvta.to.shared.u64 t, %1; cvt.u32.u64 %0, t; }"
        : "=r"(a) : "l"(p));
    return a;
}

__device__ __forceinline__ void mmah(float c[4], const uint32_t a[4],
                                     uint32_t b0, uint32_t b1) {
    asm volatile(
        "mma.sync.aligned.m16n8k16.row.col.f32.f16.f16.f32 "
        "{%0,%1,%2,%3}, {%4,%5,%6,%7}, {%8,%9}, {%0,%1,%2,%3};"
        : "+f"(c[0]), "+f"(c[1]), "+f"(c[2]), "+f"(c[3])
        : "r"(a[0]), "r"(a[1]), "r"(a[2]), "r"(a[3]), "r"(b0), "r"(b1));
}

__device__ __forceinline__ void ldsm4(uint32_t r[4], uint32_t addr) {
    asm volatile("ldmatrix.sync.aligned.m8n8.x4.shared.b16 {%0,%1,%2,%3}, [%4];"
                 : "=r"(r[0]), "=r"(r[1]), "=r"(r[2]), "=r"(r[3]) : "r"(addr));
}

__device__ __forceinline__ void ldsm4t(uint32_t r[4], uint32_t addr) {
    asm volatile("ldmatrix.sync.aligned.m8n8.x4.trans.shared.b16 {%0,%1,%2,%3}, [%4];"
                 : "=r"(r[0]), "=r"(r[1]), "=r"(r[2]), "=r"(r[3]) : "r"(addr));
}

#define CP16(dst, src) \
    asm volatile("cp.async.cg.shared.global [%0], [%1], 16;" \
                 :: "r"(dst), "l"(src) : "memory")
#define CPCOMMIT() asm volatile("cp.async.commit_group;" ::: "memory")
#define CPWAIT2()  asm volatile("cp.async.wait_group 2;" ::: "memory")

// ---------------------------------------------------------------------------
// 0) zero expert counters
// ---------------------------------------------------------------------------
__global__ void zero_counts_kernel() {
    if (threadIdx.x < NEXP) g_count[threadIdx.x] = 0;
}

// ---------------------------------------------------------------------------
// 1) aux: router (blocks 0..1023, one warp/token, writes fp16 x) +
//         weight fp16 conversion (blocks 1024..3071, strided).
// ---------------------------------------------------------------------------
__global__ __launch_bounds__(256) void aux_kernel(const float* __restrict__ x,
                                                  const float* __restrict__ Wg,
                                                  const float4* __restrict__ W1,
                                                  const float4* __restrict__ W3,
                                                  const float4* __restrict__ W2) {
    if (blockIdx.x < 1024) {
        // ---- router ----
        const int warp = (blockIdx.x * 256 + threadIdx.x) >> 5;
        const int lane = threadIdx.x & 31;

        const float* xr = x + (size_t)warp * DDIM;
        __half* xh = g_X + (size_t)warp * DDIM;
        float acc[NEXP];
#pragma unroll
        for (int e = 0; e < NEXP; e++) acc[e] = 0.f;

        for (int d = lane; d < DDIM; d += 32) {
            const float xv = xr[d];
            xh[d] = __float2half_rn(xv);
            const float4 w0 = *reinterpret_cast<const float4*>(Wg + (size_t)d * NEXP);
            const float4 w1 = *reinterpret_cast<const float4*>(Wg + (size_t)d * NEXP + 4);
            acc[0] += xv * w0.x; acc[1] += xv * w0.y; acc[2] += xv * w0.z; acc[3] += xv * w0.w;
            acc[4] += xv * w1.x; acc[5] += xv * w1.y; acc[6] += xv * w1.z; acc[7] += xv * w1.w;
        }
#pragma unroll
        for (int off = 16; off > 0; off >>= 1) {
#pragma unroll
            for (int e = 0; e < NEXP; e++)
                acc[e] += __shfl_xor_sync(0xFFFFFFFFu, acc[e], off);
        }

        if (lane == 0) {
            int i0 = 0; float v0 = acc[0];
#pragma unroll
            for (int e = 1; e < NEXP; e++) if (acc[e] > v0) { v0 = acc[e]; i0 = e; }
            int i1 = -1; float v1 = -INFINITY;
#pragma unroll
            for (int e = 0; e < NEXP; e++)
                if (e != i0 && acc[e] > v1) { v1 = acc[e]; i1 = e; }

            const float e1 = expf(v1 - v0);
            const float inv = 1.f / (1.f + e1);
            g_gate[warp * 2 + 0] = inv;
            g_gate[warp * 2 + 1] = e1 * inv;

            int p0 = atomicAdd(&g_count[i0], 1);
            g_rows[i0 * TOK + p0] = warp;
            g_slot[i0 * TOK + p0] = warp * 2;
            int p1 = atomicAdd(&g_count[i1], 1);
            g_rows[i1 * TOK + p1] = warp;
            g_slot[i1 * TOK + p1] = warp * 2 + 1;
        }
    } else {
        // ---- weight conversion ----
        const size_t total = 3 * NW4;
        const size_t stride = (size_t)2048 * 256;
        for (size_t i = (size_t)(blockIdx.x - 1024) * 256 + threadIdx.x;
             i < total; i += stride) {
            const float4* src; __half2* dst; size_t off;
            if (i < NW4)            { src = W1; dst = (__half2*)g_W1h; off = i; }
            else if (i < 2 * NW4)   { src = W3; dst = (__half2*)g_W3h; off = i - NW4; }
            else                    { src = W2; dst = (__half2*)g_W2h; off = i - 2 * NW4; }
            float4 v = src[off];
            dst[off * 2]     = __floats2half2_rn(v.x, v.y);
            dst[off * 2 + 1] = __floats2half2_rn(v.z, v.w);
        }
    }
}

// ---------------------------------------------------------------------------
// 2) Grouped dual GEMM + SwiGLU, fp16 HMMA. Block 256x64, 512 threads,
//    16 warps (8m x 2n), warp 32x32 dual. BK=64, 4-stage cp.async.
// Stage (bytes): A[256 x 64k] @0 (32768, 128B rows, chunk^=(row&7)),
//                B1[64k x 64n] @32768 (8192), B3 @40960 (8192). Stage 49152.
// ---------------------------------------------------------------------------
#define G1_SMEM_BYTES (1024 + 4 * 49152)
__global__ __launch_bounds__(512, 1) void gemm1_kernel() {
    extern __shared__ uint32_t dsm[];
    int* stok = reinterpret_cast<int*>(dsm);
    const uint32_t sb = smem_u32(dsm) + 1024;

    const int e   = blockIdx.y >> 5;
    const int mt  = blockIdx.y & 31;
    const int cnt = g_count[e];
    const int m0  = mt * 256;
    if (m0 >= cnt) return;
    const int n0 = blockIdx.x * 64;

    const int tid  = threadIdx.x;
    const int warp = tid >> 5;
    const int lane = tid & 31;
    const int wm = warp >> 1;      // 0..7
    const int wn = warp & 1;       // 0..1
    const int g  = lane >> 2;
    const int t  = lane & 3;

    if (tid < 256) {
        const int m = m0 + tid;
        stok[tid] = (m < cnt) ? g_rows[e * TOK + m] : g_rows[e * TOK];
    }
    __syncthreads();
    int tokp[4];
#pragma unroll
    for (int p = 0; p < 4; p++) tokp[p] = stok[p * 64 + (tid >> 3)];

    const __half* W1e = g_W1h + (size_t)e * DDIM * FDIM + n0;
    const __half* W3e = g_W3h + (size_t)e * DDIM * FDIM + n0;

    float acc1[2][4][4], acc3[2][4][4];
#pragma unroll
    for (int i = 0; i < 2; i++)
#pragma unroll
        for (int j = 0; j < 4; j++)
#pragma unroll
            for (int r = 0; r < 4; r++) { acc1[i][j][r] = 0.f; acc3[i][j][r] = 0.f; }

    const int rA = tid >> 3;       // 0..63
    const int cA = tid & 7;        // chunk 0..7
    const int kB = tid >> 3;       // 0..63
    const int cB = tid & 7;        // chunk 0..7

    auto issue = [&](int s, int k0) {
        const uint32_t base = sb + s * 49152;
#pragma unroll
        for (int p = 0; p < 4; p++) {
            const int r = p * 64 + rA;
            const int cs = cA ^ (r & 7);
            CP16(base + (uint32_t)(r * 128 + cs * 16),
                 g_X + (size_t)tokp[p] * DDIM + k0 + cA * 8);
        }
        {
            const int cs = cB ^ (kB & 7);
            CP16(base + 32768u + (uint32_t)(kB * 128 + cs * 16),
                 W1e + (size_t)(k0 + kB) * FDIM + cB * 8);
            CP16(base + 40960u + (uint32_t)(kB * 128 + cs * 16),
                 W3e + (size_t)(k0 + kB) * FDIM + cB * 8);
        }
        CPCOMMIT();
    };

    issue(0, 0); issue(1, BK); issue(2, 2 * BK);

    const int NCH = DDIM / BK;  // 16
    for (int c = 0; c < NCH; c++) {
        CPWAIT2();
        __syncthreads();
        if (c + 3 < NCH) issue((c + 3) & 3, (c + 3) * BK); else CPCOMMIT();

        const uint32_t sA  = sb + (c & 3) * 49152;
        const uint32_t sB1 = sA + 32768u;
        const uint32_t sB3 = sA + 40960u;
#pragma unroll
        for (int s = 0; s < 4; s++) {
            uint32_t af[2][4];
#pragma unroll
            for (int i = 0; i < 2; i++) {
                const int row = wm * 32 + i * 16 + (lane & 15);
                const int cc = 2 * s + (lane >> 4);
                const int cs = cc ^ (row & 7);
                ldsm4(af[i], sA + (uint32_t)(row * 128 + cs * 16));
            }
            const int kk = s * 16 + (lane & 7) + (lane & 8);
            uint32_t bf1[2][4], bf3[2][4];
#pragma unroll
            for (int jj = 0; jj < 2; jj++) {
                const int ci = wn * 4 + jj * 2 + (lane >> 4);
                const int cs = ci ^ (kk & 7);
                ldsm4t(bf1[jj], sB1 + (uint32_t)(kk * 128 + cs * 16));
                ldsm4t(bf3[jj], sB3 + (uint32_t)(kk * 128 + cs * 16));
            }
#pragma unroll
            for (int j = 0; j < 4; j++) {
                const int jj = j >> 1, h = (j & 1) * 2;
#pragma unroll
                for (int i = 0; i < 2; i++) {
                    mmah(acc1[i][j], af[i], bf1[jj][h], bf1[jj][h + 1]);
                    mmah(acc3[i][j], af[i], bf3[jj][h], bf3[jj][h + 1]);
                }
            }
        }
    }

    __half* Hbase = g_Hh + (size_t)e * TOK * FDIM;
    const int lim = cnt - m0;
#pragma unroll
    for (int i = 0; i < 2; i++) {
        const int lrow0 = wm * 32 + i * 16 + g;
        const int lrow1 = lrow0 + 8;
#pragma unroll
        for (int j = 0; j < 4; j++) {
            const int col = n0 + wn * 32 + j * 8 + 2 * t;
            if (lrow0 < lim) {
                const float z0 = acc1[i][j][0], z1 = acc1[i][j][1];
                __half2 hv = __floats2half2_rn(
                    (z0 / (1.f + __expf(-z0))) * acc3[i][j][0],
                    (z1 / (1.f + __expf(-z1))) * acc3[i][j][1]);
                *reinterpret_cast<__half2*>(Hbase + (size_t)(m0 + lrow0) * FDIM + col) = hv;
            }
            if (lrow1 < lim) {
                const float z2 = acc1[i][j][2], z3 = acc1[i][j][3];
                __half2 hv = __floats2half2_rn(
                    (z2 / (1.f + __expf(-z2))) * acc3[i][j][2],
                    (z3 / (1.f + __expf(-z3))) * acc3[i][j][3]);
                *reinterpret_cast<__half2*>(Hbase + (size_t)(m0 + lrow1) * FDIM + col) = hv;
            }
        }
    }
}

// ---------------------------------------------------------------------------
// 3) Grouped GEMM2, fp16 HMMA. Block 256x128, 512 threads, 16 warps (4m x 4n),
//    warp 64x32. BK=64, 4-stage. Stage: A @0 (32768), B[64k x 128n] @32768
//    (16384, 256B rows / 16 chunks, chunk^=(k&7)). Stage 49152.
// ---------------------------------------------------------------------------
#define G2_SMEM_BYTES (4 * 49152)
__global__ __launch_bounds__(512, 1) void gemm2_kernel() {
    extern __shared__ uint32_t dsm[];
    const uint32_t sb = smem_u32(dsm);

    const int e   = blockIdx.y >> 5;
    const int mt  = blockIdx.y & 31;
    const int cnt = g_count[e];
    const int m0  = mt * 256;
    if (m0 >= cnt) return;
    const int n0 = blockIdx.x * 128;

    const int tid  = threadIdx.x;
    const int warp = tid >> 5;
    const int lane = tid & 31;
    const int wm = warp >> 2;      // 0..3
    const int wn = warp & 3;       // 0..3
    const int g  = lane >> 2;
    const int t  = lane & 3;

    const __half* Hbase = g_Hh + ((size_t)e * TOK + m0) * FDIM;
    const __half* W2e   = g_W2h + (size_t)e * FDIM * DDIM + n0;

    float acc[4][4][4];
#pragma unroll
    for (int i = 0; i < 4; i++)
#pragma unroll
        for (int j = 0; j < 4; j++)
#pragma unroll
            for (int r = 0; r < 4; r++) acc[i][j][r] = 0.f;

    const int rA = tid >> 3;
    const int cA = tid & 7;
    const int kB = tid >> 4;       // 0..31
    const int cB = tid & 15;       // chunk 0..15

    auto issue = [&](int s, int k0) {
        const uint32_t base = sb + s * 49152;
#pragma unroll
        for (int p = 0; p < 4; p++) {
            const int r = p * 64 + rA;
            const int cs = cA ^ (r & 7);
            CP16(base + (uint32_t)(r * 128 + cs * 16),
                 Hbase + (size_t)r * FDIM + k0 + cA * 8);
        }
#pragma unroll
        for (int p = 0; p < 2; p++) {
            const int k = p * 32 + kB;
            const int cs = cB ^ (k & 7);
            CP16(base + 32768u + (uint32_t)(k * 256 + cs * 16),
                 W2e + (size_t)(k0 + k) * DDIM + cB * 8);
        }
        CPCOMMIT();
    };

    issue(0, 0); issue(1, BK); issue(2, 2 * BK);

    const int NCH = FDIM / BK;  // 32
    for (int c = 0; c < NCH; c++) {
        CPWAIT2();
        __syncthreads();
        if (c + 3 < NCH) issue((c + 3) & 3, (c + 3) * BK); else CPCOMMIT();

        const uint32_t sA = sb + (c & 3) * 49152;
        const uint32_t sB = sA + 32768u;
#pragma unroll
        for (int s = 0; s < 4; s++) {
            uint32_t af[4][4];
#pragma unroll
            for (int i = 0; i < 4; i++) {
                const int row = wm * 64 + i * 16 + (lane & 15);
                const int cc = 2 * s + (lane >> 4);
                const int cs = cc ^ (row & 7);
                ldsm4(af[i], sA + (uint32_t)(row * 128 + cs * 16));
            }
            const int kk = s * 16 + (lane & 7) + (lane & 8);
            uint32_t bf[2][4];
#pragma unroll
            for (int jj = 0; jj < 2; jj++) {
                const int ci = wn * 4 + jj * 2 + (lane >> 4);
                const int cs = ci ^ (kk & 7);
                ldsm4t(bf[jj], sB + (uint32_t)(kk * 256 + cs * 16));
            }
#pragma unroll
            for (int j = 0; j < 4; j++) {
                const int jj = j >> 1, h = (j & 1) * 2;
#pragma unroll
                for (int i = 0; i < 4; i++)
                    mmah(acc[i][j], af[i], bf[jj][h], bf[jj][h + 1]);
            }
        }
    }

    const int lim = cnt - m0;
#pragma unroll
    for (int i = 0; i < 4; i++) {
        const int lrow0 = wm * 64 + i * 16 + g;
        const int lrow1 = lrow0 + 8;
        const int slot0 = (lrow0 < lim) ? g_slot[e * TOK + m0 + lrow0] : -1;
        const int slot1 = (lrow1 < lim) ? g_slot[e * TOK + m0 + lrow1] : -1;
#pragma unroll
        for (int j = 0; j < 4; j++) {
            const int col = n0 + wn * 32 + j * 8 + 2 * t;
            if (slot0 >= 0)
                *reinterpret_cast<float2*>(g_Y + (size_t)slot0 * DDIM + col) =
                    make_float2(acc[i][j][0], acc[i][j][1]);
            if (slot1 >= 0)
                *reinterpret_cast<float2*>(g_Y + (size_t)slot1 * DDIM + col) =
                    make_float2(acc[i][j][2], acc[i][j][3]);
        }
    }
}

// ---------------------------------------------------------------------------
// 4) Combine
// ---------------------------------------------------------------------------
__global__ __launch_bounds__(256) void combine_kernel(float* __restrict__ out) {
    const int tk = blockIdx.x;
    const int d = threadIdx.x * 4;
    const float g0 = g_gate[tk * 2 + 0];
    const float g1 = g_gate[tk * 2 + 1];
    const float4 y0 = *reinterpret_cast<const float4*>(g_Y + ((size_t)tk * 2 + 0) * DDIM + d);
    const float4 y1 = *reinterpret_cast<const float4*>(g_Y + ((size_t)tk * 2 + 1) * DDIM + d);
    float4 o;
    o.x = g0 * y0.x + g1 * y1.x;
    o.y = g0 * y0.y + g1 * y1.y;
    o.z = g0 * y0.z + g1 * y1.z;
    o.w = g0 * y0.w + g1 * y1.w;
    *reinterpret_cast<float4*>(out + (size_t)tk * DDIM + d) = o;
}

// ---------------------------------------------------------------------------
// Entry
// ---------------------------------------------------------------------------
extern "C" void kernel_launch(void* const* d_in, const int* in_sizes, int n_in,
                              void* d_out, int out_size) {
    const float* x  = (const float*)d_in[0];
    const float* Wg = (const float*)d_in[1];
    const float* W1 = (const float*)d_in[2];
    const float* W3 = (const float*)d_in[3];
    const float* W2 = (const float*)d_in[4];
    float* out = (float*)d_out;

    static int attr_done = 0;
    if (!attr_done) {
        cudaFuncSetAttribute(gemm1_kernel,
                             cudaFuncAttributeMaxDynamicSharedMemorySize, G1_SMEM_BYTES);
        cudaFuncSetAttribute(gemm2_kernel,
                             cudaFuncAttributeMaxDynamicSharedMemorySize, G2_SMEM_BYTES);
        attr_done = 1;
    }

    zero_counts_kernel<<<1, 32>>>();
    aux_kernel<<<3072, 256>>>(x, Wg, (const float4*)W1, (const float4*)W3,
                              (const float4*)W2);
    gemm1_kernel<<<dim3(FDIM / 64, NEXP * (TOK / 256)), 512, G1_SMEM_BYTES>>>();
    gemm2_kernel<<<dim3(DDIM / 128, NEXP * (TOK / 256)), 512, G2_SMEM_BYTES>>>();
    combine_kernel<<<TOK, 256>>>(out);
}